// round 9
// baseline (speedup 1.0000x reference)
#include <cuda_runtime.h>
#include <cuda_bf16.h>
#include <cstdint>

#define HID 128
#define NMAX 100000
#define EMAX 800000

__device__ float  g_buf0[(size_t)NMAX * HID];  // xw1
__device__ float  g_y2  [(size_t)NMAX * 4];    // relu(h) @ V
__device__ float  g_c   [(size_t)NMAX * 4];    // layer-2 collapsed aggregate
__device__ float  g_VT  [4 * HID];             // (W2 @ WlinPacked)^T : VT[j][k]
__device__ ushort g_Whi [128 * 136];           // W1 hi, padded [k][n] layout
__device__ ushort g_Wlo [128 * 136];           // W1 lo
__device__ int    g_cnt [NMAX];                // CSR degree
__device__ int    g_off [NMAX + 1];            // CSR offsets
__device__ int    g_cur [NMAX];                // CSR fill cursors
__device__ int2   g_epk [EMAX];                // CSR edges: {src, w bits}

__device__ __forceinline__ uint32_t smem_u32(const void* p) {
    uint32_t a;
    asm("{ .reg .u64 t; cvta.to.shared.u64 t, %1; cvt.u32.u64 %0, t; }"
        : "=r"(a) : "l"(p));
    return a;
}

#define LDM_X4(r0, r1, r2, r3, a)                                             \
    asm volatile("ldmatrix.sync.aligned.m8n8.x4.shared.b16 {%0,%1,%2,%3}, [%4];" \
                 : "=r"(r0), "=r"(r1), "=r"(r2), "=r"(r3) : "r"(a))
#define LDM_X4T(r0, r1, r2, r3, a)                                            \
    asm volatile("ldmatrix.sync.aligned.m8n8.x4.trans.shared.b16 {%0,%1,%2,%3}, [%4];" \
                 : "=r"(r0), "=r"(r1), "=r"(r2), "=r"(r3) : "r"(a))
#define MMA_BF16(d, a, b)                                                     \
    asm volatile("mma.sync.aligned.m16n8k16.row.col.f32.bf16.bf16.f32 "       \
                 "{%0,%1,%2,%3}, {%4,%5,%6,%7}, {%8,%9}, {%0,%1,%2,%3};"      \
                 : "+f"((d)[0]), "+f"((d)[1]), "+f"((d)[2]), "+f"((d)[3])     \
                 : "r"((a)[0]), "r"((a)[1]), "r"((a)[2]), "r"((a)[3]),        \
                   "r"((b)[0]), "r"((b)[1]))

__device__ __forceinline__ void split2(float f, ushort& h, ushort& l) {
    uint32_t fb = __float_as_uint(f);
    h = (ushort)(fb >> 16);
    float lo = f - __uint_as_float(fb & 0xFFFF0000u);   // exact
    __nv_bfloat16 bl = __float2bfloat16_rn(lo);
    l = *(ushort*)&bl;
}

// ---------------------------------------------------------------------------
// Pre-split W1 into bf16 hi/lo, padded [k][136] layout.
// ---------------------------------------------------------------------------
__global__ void wsplit_kernel(const float* __restrict__ W,
                              ushort* __restrict__ Whi, ushort* __restrict__ Wlo)
{
    int i = blockIdx.x * blockDim.x + threadIdx.x;
    if (i >= 128 * 32) return;
    int k = i >> 5, q = i & 31;
    float4 v = __ldg((const float4*)(W + (size_t)k * HID) + q);
    float f[4] = {v.x, v.y, v.z, v.w};
    ushort h[4], l[4];
#pragma unroll
    for (int j = 0; j < 4; j++) split2(f[j], h[j], l[j]);
    uint2 hp = make_uint2((uint32_t)h[0] | ((uint32_t)h[1] << 16),
                          (uint32_t)h[2] | ((uint32_t)h[3] << 16));
    uint2 lp = make_uint2((uint32_t)l[0] | ((uint32_t)l[1] << 16),
                          (uint32_t)l[2] | ((uint32_t)l[3] << 16));
    *(uint2*)(Whi + (size_t)k * 136 + q * 4) = hp;
    *(uint2*)(Wlo + (size_t)k * 136 + q * 4) = lp;
}

// ---------------------------------------------------------------------------
// VT[j][k] = sum_c W2[k,c] * wl_j[c]
// ---------------------------------------------------------------------------
__global__ void vpack_kernel(const float* __restrict__ W2,
                             const float* __restrict__ Wlin,
                             float* __restrict__ VT)
{
    int i = threadIdx.x;          // 0..511
    int k = i >> 2, j = i & 3;
    const float* wl = Wlin + (j >> 1) * 256 + (j & 1) * 128;
    const float* wr = W2 + (size_t)k * HID;
    float acc = 0.f;
#pragma unroll 8
    for (int c = 0; c < HID; c++) acc += __ldg(wr + c) * __ldg(wl + c);
    VT[j * HID + k] = acc;
}

// ---------------------------------------------------------------------------
// CSR build: histogram, scan, reorder
// ---------------------------------------------------------------------------
__global__ void hist_kernel(const int* __restrict__ ei, int E, int* __restrict__ cnt)
{
    int i = blockIdx.x * blockDim.x + threadIdx.x;
    int e0 = i * 4;
    if (e0 >= E) return;
    if (e0 + 4 <= E) {
        int4 d = __ldg((const int4*)(ei + E) + i);
        atomicAdd(&cnt[d.x], 1); atomicAdd(&cnt[d.y], 1);
        atomicAdd(&cnt[d.z], 1); atomicAdd(&cnt[d.w], 1);
    } else {
        for (int e = e0; e < E; e++) atomicAdd(&cnt[__ldg(ei + E + e)], 1);
    }
}

__global__ __launch_bounds__(1024) void scan_kernel(
    const int* __restrict__ cnt, int* __restrict__ off, int* __restrict__ cur, int n)
{
    __shared__ int ssum[1024];
    int t = threadIdx.x;
    int per = (n + 1023) / 1024;
    int s0 = t * per;
    int s1 = s0 + per; if (s1 > n) s1 = n;
    int sum = 0;
    for (int i = s0; i < s1; i++) sum += cnt[i];
    ssum[t] = sum;
    __syncthreads();
    for (int o = 1; o < 1024; o <<= 1) {
        int v = (t >= o) ? ssum[t - o] : 0;
        __syncthreads();
        ssum[t] += v;
        __syncthreads();
    }
    int run = (t == 0) ? 0 : ssum[t - 1];
    for (int i = s0; i < s1; i++) {
        off[i] = run; cur[i] = run;
        run += cnt[i];
    }
    if (t == 1023) off[n] = ssum[1023];
}

__global__ void reorder_kernel(const int* __restrict__ ei,
                               const float* __restrict__ ew, int E,
                               int* __restrict__ cur, int2* __restrict__ epk)
{
    int i = blockIdx.x * blockDim.x + threadIdx.x;
    int e0 = i * 4;
    if (e0 >= E) return;
    if (e0 + 4 <= E) {
        int4   s4 = __ldg((const int4*)ei + i);
        int4   d4 = __ldg((const int4*)(ei + E) + i);
        float4 w4 = __ldg((const float4*)ew + i);
        int   s[4] = {s4.x, s4.y, s4.z, s4.w};
        int   d[4] = {d4.x, d4.y, d4.z, d4.w};
        float w[4] = {w4.x, w4.y, w4.z, w4.w};
#pragma unroll
        for (int j = 0; j < 4; j++) {
            int pos = atomicAdd(&cur[d[j]], 1);
            epk[pos] = make_int2(s[j], __float_as_int(w[j]));
        }
    } else {
        for (int e = e0; e < E; e++) {
            int pos = atomicAdd(&cur[__ldg(ei + E + e)], 1);
            epk[pos] = make_int2(__ldg(ei + e), __float_as_int(__ldg(ew + e)));
        }
    }
}

// ===========================================================================
// GEMM1 (HMMA bf16x3): Y[n,128] = X @ W1. Pre-split W; no zero pass.
// ===========================================================================
#define LDS_ 136
#define OFF_XH 0
#define OFF_XL (64 * LDS_ * 2)
#define OFF_WH (2 * 64 * LDS_ * 2)
#define OFF_WL (OFF_WH + 128 * LDS_ * 2)
#define GEMM_SMEM_BYTES (OFF_WL + 128 * LDS_ * 2)   // 104,448 B
#define W_U4 (128 * LDS_ * 2 / 16)

__global__ __launch_bounds__(256, 2) void gemm_mma_kernel(
    const float* __restrict__ X,
    const ushort* __restrict__ Whi, const ushort* __restrict__ Wlo,
    float* __restrict__ Y, int n)
{
    extern __shared__ char sm[];
    const int t   = threadIdx.x;
    const int lid = t & 31;
    const int wid = t >> 5;
    const int row0 = blockIdx.x * 64;

    {
        const uint4* wh4 = (const uint4*)Whi;
        const uint4* wl4 = (const uint4*)Wlo;
        uint4* dh = (uint4*)(sm + OFF_WH);
        uint4* dl = (uint4*)(sm + OFF_WL);
        for (int i = t; i < W_U4; i += 256) {
            dh[i] = __ldg(wh4 + i);
            dl[i] = __ldg(wl4 + i);
        }
    }

    for (int i = t; i < 64 * 32; i += 256) {
        int m = i >> 5, q = i & 31;
        int r = row0 + m;
        int rc = r < n ? r : 0;
        float4 v = __ldg((const float4*)(X + (size_t)rc * HID) + q);
        float f[4] = {v.x, v.y, v.z, v.w};
        ushort h[4], l[4];
#pragma unroll
        for (int j = 0; j < 4; j++) split2(f[j], h[j], l[j]);
        uint2 hp = make_uint2((uint32_t)h[0] | ((uint32_t)h[1] << 16),
                              (uint32_t)h[2] | ((uint32_t)h[3] << 16));
        uint2 lp = make_uint2((uint32_t)l[0] | ((uint32_t)l[1] << 16),
                              (uint32_t)l[2] | ((uint32_t)l[3] << 16));
        size_t off = ((size_t)m * LDS_ + q * 4) * 2;
        *(uint2*)(sm + OFF_XH + off) = hp;
        *(uint2*)(sm + OFF_XL + off) = lp;
    }
    __syncthreads();

    const int wm = wid & 1;
    const int wn = wid >> 1;
    const int mat  = lid >> 3;
    const int rsel = (mat & 1) * 8 + (lid & 7);
    const int csel = (mat >> 1) * 8;

    const uint32_t sb = smem_u32(sm);
    uint32_t aH = sb + OFF_XH + (uint32_t)(((wm * 32 + rsel) * LDS_ + csel) * 2);
    uint32_t aL = aH + (OFF_XL - OFF_XH);
    uint32_t bH = sb + OFF_WH + (uint32_t)((rsel * LDS_ + wn * 32 + csel) * 2);
    uint32_t bL = bH + (OFF_WL - OFF_WH);

    float acc[2][4][4];
#pragma unroll
    for (int mi = 0; mi < 2; mi++)
#pragma unroll
        for (int nj = 0; nj < 4; nj++)
#pragma unroll
            for (int e = 0; e < 4; e++) acc[mi][nj][e] = 0.f;

#pragma unroll
    for (int ks = 0; ks < 8; ks++) {
        const uint32_t ao = ks * 32;
        const uint32_t bo = (uint32_t)(ks * 16 * LDS_ * 2);

        uint32_t ah[2][4], al[2][4];
        LDM_X4(ah[0][0], ah[0][1], ah[0][2], ah[0][3], aH + ao);
        LDM_X4(ah[1][0], ah[1][1], ah[1][2], ah[1][3], aH + ao + 16 * LDS_ * 2);
        LDM_X4(al[0][0], al[0][1], al[0][2], al[0][3], aL + ao);
        LDM_X4(al[1][0], al[1][1], al[1][2], al[1][3], aL + ao + 16 * LDS_ * 2);

        uint32_t bh[4][2], bl[4][2];
#pragma unroll
        for (int g = 0; g < 2; g++) {
            LDM_X4T(bh[g * 2][0], bh[g * 2][1], bh[g * 2 + 1][0], bh[g * 2 + 1][1],
                    bH + bo + g * 32);
            LDM_X4T(bl[g * 2][0], bl[g * 2][1], bl[g * 2 + 1][0], bl[g * 2 + 1][1],
                    bL + bo + g * 32);
        }

#pragma unroll
        for (int mi = 0; mi < 2; mi++)
#pragma unroll
            for (int nj = 0; nj < 4; nj++) {
                MMA_BF16(acc[mi][nj], ah[mi], bh[nj]);
                MMA_BF16(acc[mi][nj], ah[mi], bl[nj]);
                MMA_BF16(acc[mi][nj], al[mi], bh[nj]);
            }
    }

    const int g  = lid >> 2;
    const int c2 = (lid & 3) * 2;
#pragma unroll
    for (int mi = 0; mi < 2; mi++) {
        int rbase = row0 + wm * 32 + mi * 16;
        int r1 = rbase + g, r2 = rbase + g + 8;
#pragma unroll
        for (int nj = 0; nj < 4; nj++) {
            int col = wn * 32 + nj * 8 + c2;
            if (r1 < n)
                *(float2*)(Y + (size_t)r1 * HID + col) =
                    make_float2(acc[mi][nj][0], acc[mi][nj][1]);
            if (r2 < n)
                *(float2*)(Y + (size_t)r2 * HID + col) =
                    make_float2(acc[mi][nj][2], acc[mi][nj][3]);
        }
    }
}

// ---------------------------------------------------------------------------
// Fused CSR scatter + projection: one warp per dst node.
//   acc = sum_{edges->node} w * xw1[src]   (registers, no atomics)
//   y2[node] = relu(acc) @ V ; c[node] = 0
// ---------------------------------------------------------------------------
__global__ __launch_bounds__(256) void scatter_csr_fused_kernel(
    const float* __restrict__ F, const int* __restrict__ off,
    const int2* __restrict__ epk, const float* __restrict__ VT,
    float* __restrict__ y2, float* __restrict__ c, int n)
{
    int node = (int)(((long long)blockIdx.x * blockDim.x + threadIdx.x) >> 5);
    int lane = threadIdx.x & 31;
    if (node >= n) return;

    float4 vv[4];
#pragma unroll
    for (int j = 0; j < 4; j++)
        vv[j] = __ldg((const float4*)(VT + j * HID) + lane);

    int b = __ldg(off + node);
    int e = __ldg(off + node + 1);

    float4 acc = make_float4(0.f, 0.f, 0.f, 0.f);
    int i = b;
    for (; i + 4 <= e; i += 4) {
        int2 e0 = __ldg(epk + i),     e1 = __ldg(epk + i + 1);
        int2 e2 = __ldg(epk + i + 2), e3 = __ldg(epk + i + 3);
        float4 v0 = __ldg((const float4*)(F + (size_t)e0.x * HID) + lane);
        float4 v1 = __ldg((const float4*)(F + (size_t)e1.x * HID) + lane);
        float4 v2 = __ldg((const float4*)(F + (size_t)e2.x * HID) + lane);
        float4 v3 = __ldg((const float4*)(F + (size_t)e3.x * HID) + lane);
        float w0 = __int_as_float(e0.y), w1 = __int_as_float(e1.y);
        float w2 = __int_as_float(e2.y), w3 = __int_as_float(e3.y);
        acc.x = fmaf(w0, v0.x, fmaf(w1, v1.x, fmaf(w2, v2.x, fmaf(w3, v3.x, acc.x))));
        acc.y = fmaf(w0, v0.y, fmaf(w1, v1.y, fmaf(w2, v2.y, fmaf(w3, v3.y, acc.y))));
        acc.z = fmaf(w0, v0.z, fmaf(w1, v1.z, fmaf(w2, v2.z, fmaf(w3, v3.z, acc.z))));
        acc.w = fmaf(w0, v0.w, fmaf(w1, v1.w, fmaf(w2, v2.w, fmaf(w3, v3.w, acc.w))));
    }
    for (; i < e; i++) {
        int2 ed = __ldg(epk + i);
        float w = __int_as_float(ed.y);
        float4 v = __ldg((const float4*)(F + (size_t)ed.x * HID) + lane);
        acc.x = fmaf(w, v.x, acc.x); acc.y = fmaf(w, v.y, acc.y);
        acc.z = fmaf(w, v.z, acc.z); acc.w = fmaf(w, v.w, acc.w);
    }

    // relu + 4 dot products with V
    float rx = fmaxf(acc.x, 0.f), ry = fmaxf(acc.y, 0.f);
    float rz = fmaxf(acc.z, 0.f), rw = fmaxf(acc.w, 0.f);
    float d[4];
#pragma unroll
    for (int j = 0; j < 4; j++)
        d[j] = rx * vv[j].x + ry * vv[j].y + rz * vv[j].z + rw * vv[j].w;
#pragma unroll
    for (int o = 16; o > 0; o >>= 1) {
#pragma unroll
        for (int j = 0; j < 4; j++)
            d[j] += __shfl_xor_sync(0xFFFFFFFFu, d[j], o);
    }
    if (lane == 0) {
        ((float4*)y2)[node] = make_float4(d[0], d[1], d[2], d[3]);
        ((float4*)c)[node]  = make_float4(0.f, 0.f, 0.f, 0.f);
    }
}

// ---------------------------------------------------------------------------
// Narrow scatter (layer 2 collapsed): c[dst] += w_e * y2[src]. 4 edges/thread.
// ---------------------------------------------------------------------------
__global__ __launch_bounds__(256) void scatter4_kernel(
    const float* __restrict__ y2, const int* __restrict__ ei,
    const float* __restrict__ ew, float* __restrict__ c, int E)
{
    int tI = blockIdx.x * blockDim.x + threadIdx.x;
    int e0 = tI * 4;
    if (e0 >= E) return;

    if (e0 + 4 <= E) {
        int4   s4 = __ldg((const int4*)ei + tI);
        int4   d4 = __ldg((const int4*)(ei + E) + tI);
        float4 w4 = __ldg((const float4*)ew + tI);
        int   s[4] = {s4.x, s4.y, s4.z, s4.w};
        int   d[4] = {d4.x, d4.y, d4.z, d4.w};
        float w[4] = {w4.x, w4.y, w4.z, w4.w};
        float4 v[4];
#pragma unroll
        for (int j = 0; j < 4; j++) v[j] = __ldg((const float4*)y2 + s[j]);
#pragma unroll
        for (int j = 0; j < 4; j++) {
            v[j].x *= w[j]; v[j].y *= w[j]; v[j].z *= w[j]; v[j].w *= w[j];
            float* p = c + (size_t)d[j] * 4;
            asm volatile("red.global.add.v4.f32 [%0], {%1,%2,%3,%4};"
                         :: "l"(p), "f"(v[j].x), "f"(v[j].y), "f"(v[j].z), "f"(v[j].w)
                         : "memory");
        }
    } else {
        for (int e = e0; e < E; e++) {
            int   s = __ldg(ei + e);
            int   d = __ldg(ei + E + e);
            float w = __ldg(ew + e);
            float4 v = __ldg((const float4*)y2 + s);
            v.x *= w; v.y *= w; v.z *= w; v.w *= w;
            float* p = c + (size_t)d * 4;
            asm volatile("red.global.add.v4.f32 [%0], {%1,%2,%3,%4};"
                         :: "l"(p), "f"(v.x), "f"(v.y), "f"(v.z), "f"(v.w) : "memory");
        }
    }
}

// ---------------------------------------------------------------------------
// Pair epilogue: out[p] = (c[a].0 + c[b].1, c[a].2 + c[b].3)
// ---------------------------------------------------------------------------
__global__ __launch_bounds__(256) void pair_small_kernel(
    const float* __restrict__ c, const int* __restrict__ pe,
    float* __restrict__ out, int P)
{
    int p = blockIdx.x * blockDim.x + threadIdx.x;
    if (p >= P) return;
    int a = __ldg(pe + p);
    int b = __ldg(pe + P + p);
    float4 ca = __ldg((const float4*)c + a);
    float4 cb = __ldg((const float4*)c + b);
    ((float2*)out)[p] = make_float2(ca.x + cb.y, ca.z + cb.w);
}

// ---------------------------------------------------------------------------
// Launch
// ---------------------------------------------------------------------------
extern "C" void kernel_launch(void* const* d_in, const int* in_sizes, int n_in,
                              void* d_out, int out_size)
{
    const float* x    = (const float*)d_in[0];
    const int*   ei1  = (const int*)  d_in[1];
    const int*   ei2  = (const int*)  d_in[2];
    const float* ew1  = (const float*)d_in[3];
    const float* ew2  = (const float*)d_in[4];
    const int*   pe   = (const int*)  d_in[5];
    const float* W1   = (const float*)d_in[6];
    const float* W2   = (const float*)d_in[7];
    const float* Wlin = (const float*)d_in[8];
    float* out = (float*)d_out;

    int n  = in_sizes[0] / HID;
    int E1 = in_sizes[3];
    int E2 = in_sizes[4];
    int P  = in_sizes[5] / 2;

    void *p_buf0, *p_y2, *p_c, *p_VT, *p_Whi, *p_Wlo;
    void *p_cnt, *p_off, *p_cur, *p_epk;
    cudaGetSymbolAddress(&p_buf0, g_buf0);
    cudaGetSymbolAddress(&p_y2,   g_y2);
    cudaGetSymbolAddress(&p_c,    g_c);
    cudaGetSymbolAddress(&p_VT,   g_VT);
    cudaGetSymbolAddress(&p_Whi,  g_Whi);
    cudaGetSymbolAddress(&p_Wlo,  g_Wlo);
    cudaGetSymbolAddress(&p_cnt,  g_cnt);
    cudaGetSymbolAddress(&p_off,  g_off);
    cudaGetSymbolAddress(&p_cur,  g_cur);
    cudaGetSymbolAddress(&p_epk,  g_epk);
    float*  buf0 = (float*)p_buf0;
    float*  y2   = (float*)p_y2;
    float*  c    = (float*)p_c;
    float*  VT   = (float*)p_VT;
    ushort* Whi  = (ushort*)p_Whi;
    ushort* Wlo  = (ushort*)p_Wlo;
    int*    cnt  = (int*)p_cnt;
    int*    off  = (int*)p_off;
    int*    cur  = (int*)p_cur;
    int2*   epk  = (int2*)p_epk;

    cudaFuncSetAttribute(gemm_mma_kernel,
        cudaFuncAttributeMaxDynamicSharedMemorySize, GEMM_SMEM_BYTES);

    // Precomputes
    wsplit_kernel<<<16, 256>>>(W1, Whi, Wlo);
    vpack_kernel<<<1, 512>>>(W2, Wlin, VT);

    // CSR build for edge set 1 (dst-sorted)
    cudaMemsetAsync(cnt, 0, (size_t)n * sizeof(int));
    {
        int q = (E1 + 3) / 4;
        hist_kernel<<<(q + 255) / 256, 256>>>(ei1, E1, cnt);
        scan_kernel<<<1, 1024>>>(cnt, off, cur, n);
        reorder_kernel<<<(q + 255) / 256, 256>>>(ei1, ew1, E1, cur, epk);
    }

    // GEMM1: buf0 = x @ W1
    int gemmBlocks = (n + 63) / 64;
    gemm_mma_kernel<<<gemmBlocks, 256, GEMM_SMEM_BYTES>>>(x, Whi, Wlo, buf0, n);

    // Fused CSR aggregate + relu + V projection (writes y2, zeroes c)
    {
        long long th = (long long)n * 32;
        scatter_csr_fused_kernel<<<(int)((th + 255) / 256), 256>>>(
            buf0, off, epk, VT, y2, c, n);
    }

    // Narrow scatter (layer 2 collapsed)
    {
        int threads = (E2 + 3) / 4;
        scatter4_kernel<<<(threads + 255) / 256, 256>>>(y2, ei2, ew2, c, E2);
    }

    // Pair epilogue
    pair_small_kernel<<<(P + 255) / 256, 256>>>(c, pe, out, P);
}

// round 10
// speedup vs baseline: 1.7476x; 1.7476x over previous
#include <cuda_runtime.h>
#include <cuda_bf16.h>
#include <cstdint>

#define HID 128
#define NMAX 100000
#define EMAX 800000

__device__ float  g_buf0[(size_t)NMAX * HID];  // xw1
__device__ float  g_y2  [(size_t)NMAX * 4];    // relu(h) @ V
__device__ float  g_c   [(size_t)NMAX * 4];    // layer-2 collapsed aggregate
__device__ float  g_VT  [4 * HID];             // (W2 @ WlinPacked)^T : VT[j][k]
__device__ ushort g_Whi [128 * 136];           // W1 hi, padded [k][n] layout
__device__ ushort g_Wlo [128 * 136];           // W1 lo
__device__ int    g_cnt [NMAX];                // CSR degree
__device__ int    g_off [NMAX];                // CSR segment starts
__device__ int    g_cur [NMAX];                // CSR fill cursors
__device__ int    g_tot [1];                   // allocation counter
__device__ int2   g_epk [EMAX];                // CSR edges: {src, w bits}

__device__ __forceinline__ uint32_t smem_u32(const void* p) {
    uint32_t a;
    asm("{ .reg .u64 t; cvta.to.shared.u64 t, %1; cvt.u32.u64 %0, t; }"
        : "=r"(a) : "l"(p));
    return a;
}

#define LDM_X4(r0, r1, r2, r3, a)                                             \
    asm volatile("ldmatrix.sync.aligned.m8n8.x4.shared.b16 {%0,%1,%2,%3}, [%4];" \
                 : "=r"(r0), "=r"(r1), "=r"(r2), "=r"(r3) : "r"(a))
#define LDM_X4T(r0, r1, r2, r3, a)                                            \
    asm volatile("ldmatrix.sync.aligned.m8n8.x4.trans.shared.b16 {%0,%1,%2,%3}, [%4];" \
                 : "=r"(r0), "=r"(r1), "=r"(r2), "=r"(r3) : "r"(a))
#define MMA_BF16(d, a, b)                                                     \
    asm volatile("mma.sync.aligned.m16n8k16.row.col.f32.bf16.bf16.f32 "       \
                 "{%0,%1,%2,%3}, {%4,%5,%6,%7}, {%8,%9}, {%0,%1,%2,%3};"      \
                 : "+f"((d)[0]), "+f"((d)[1]), "+f"((d)[2]), "+f"((d)[3])     \
                 : "r"((a)[0]), "r"((a)[1]), "r"((a)[2]), "r"((a)[3]),        \
                   "r"((b)[0]), "r"((b)[1]))

__device__ __forceinline__ void split2(float f, ushort& h, ushort& l) {
    uint32_t fb = __float_as_uint(f);
    h = (ushort)(fb >> 16);
    float lo = f - __uint_as_float(fb & 0xFFFF0000u);   // exact
    __nv_bfloat16 bl = __float2bfloat16_rn(lo);
    l = *(ushort*)&bl;
}

// ---------------------------------------------------------------------------
// Pre-split W1 into bf16 hi/lo, padded [k][136] layout.
// ---------------------------------------------------------------------------
__global__ void wsplit_kernel(const float* __restrict__ W,
                              ushort* __restrict__ Whi, ushort* __restrict__ Wlo)
{
    int i = blockIdx.x * blockDim.x + threadIdx.x;
    if (i >= 128 * 32) return;
    int k = i >> 5, q = i & 31;
    float4 v = __ldg((const float4*)(W + (size_t)k * HID) + q);
    float f[4] = {v.x, v.y, v.z, v.w};
    ushort h[4], l[4];
#pragma unroll
    for (int j = 0; j < 4; j++) split2(f[j], h[j], l[j]);
    uint2 hp = make_uint2((uint32_t)h[0] | ((uint32_t)h[1] << 16),
                          (uint32_t)h[2] | ((uint32_t)h[3] << 16));
    uint2 lp = make_uint2((uint32_t)l[0] | ((uint32_t)l[1] << 16),
                          (uint32_t)l[2] | ((uint32_t)l[3] << 16));
    *(uint2*)(Whi + (size_t)k * 136 + q * 4) = hp;
    *(uint2*)(Wlo + (size_t)k * 136 + q * 4) = lp;
}

// ---------------------------------------------------------------------------
// VT[j][k] = sum_c W2[k,c] * wl_j[c]
// ---------------------------------------------------------------------------
__global__ void vpack_kernel(const float* __restrict__ W2,
                             const float* __restrict__ Wlin,
                             float* __restrict__ VT)
{
    int i = threadIdx.x;          // 0..511
    int k = i >> 2, j = i & 3;
    const float* wl = Wlin + (j >> 1) * 256 + (j & 1) * 128;
    const float* wr = W2 + (size_t)k * HID;
    float acc = 0.f;
#pragma unroll 8
    for (int c = 0; c < HID; c++) acc += __ldg(wr + c) * __ldg(wl + c);
    VT[j * HID + k] = acc;
}

// ---------------------------------------------------------------------------
// CSR build: histogram -> warp-aggregated segment allocation -> reorder
// ---------------------------------------------------------------------------
__global__ void hist_kernel(const int* __restrict__ ei, int E, int* __restrict__ cnt)
{
    int i = blockIdx.x * blockDim.x + threadIdx.x;
    int e0 = i * 4;
    if (e0 >= E) return;
    if (e0 + 4 <= E) {
        int4 d = __ldg((const int4*)(ei + E) + i);
        atomicAdd(&cnt[d.x], 1); atomicAdd(&cnt[d.y], 1);
        atomicAdd(&cnt[d.z], 1); atomicAdd(&cnt[d.w], 1);
    } else {
        for (int e = e0; e < E; e++) atomicAdd(&cnt[__ldg(ei + E + e)], 1);
    }
}

// Segment allocation: warp inclusive scan of degrees, one atomicAdd per warp.
// (Segment placement is allocation-order dependent, but each node's segment
//  content/order is unchanged, so numerics match the validated path.)
__global__ __launch_bounds__(256) void alloc_kernel(
    const int* __restrict__ cnt, int* __restrict__ off, int* __restrict__ cur,
    int* __restrict__ total, int n)
{
    int i = blockIdx.x * blockDim.x + threadIdx.x;
    int lane = threadIdx.x & 31;
    int cv = (i < n) ? __ldg(cnt + i) : 0;
    int sc = cv;
#pragma unroll
    for (int o = 1; o < 32; o <<= 1) {
        int v = __shfl_up_sync(0xFFFFFFFFu, sc, o);
        if (lane >= o) sc += v;
    }
    int wsum = __shfl_sync(0xFFFFFFFFu, sc, 31);
    int base = 0;
    if (lane == 31 && wsum > 0) base = atomicAdd(total, wsum);
    base = __shfl_sync(0xFFFFFFFFu, base, 31);
    if (i < n) {
        int o = base + sc - cv;
        off[i] = o; cur[i] = o;
    }
}

__global__ void reorder_kernel(const int* __restrict__ ei,
                               const float* __restrict__ ew, int E,
                               int* __restrict__ cur, int2* __restrict__ epk)
{
    int i = blockIdx.x * blockDim.x + threadIdx.x;
    int e0 = i * 4;
    if (e0 >= E) return;
    if (e0 + 4 <= E) {
        int4   s4 = __ldg((const int4*)ei + i);
        int4   d4 = __ldg((const int4*)(ei + E) + i);
        float4 w4 = __ldg((const float4*)ew + i);
        int   s[4] = {s4.x, s4.y, s4.z, s4.w};
        int   d[4] = {d4.x, d4.y, d4.z, d4.w};
        float w[4] = {w4.x, w4.y, w4.z, w4.w};
#pragma unroll
        for (int j = 0; j < 4; j++) {
            int pos = atomicAdd(&cur[d[j]], 1);
            epk[pos] = make_int2(s[j], __float_as_int(w[j]));
        }
    } else {
        for (int e = e0; e < E; e++) {
            int pos = atomicAdd(&cur[__ldg(ei + E + e)], 1);
            epk[pos] = make_int2(__ldg(ei + e), __float_as_int(__ldg(ew + e)));
        }
    }
}

// ===========================================================================
// GEMM1 (HMMA bf16x3): Y[n,128] = X @ W1. Pre-split W; no zero pass.
// ===========================================================================
#define LDS_ 136
#define OFF_XH 0
#define OFF_XL (64 * LDS_ * 2)
#define OFF_WH (2 * 64 * LDS_ * 2)
#define OFF_WL (OFF_WH + 128 * LDS_ * 2)
#define GEMM_SMEM_BYTES (OFF_WL + 128 * LDS_ * 2)   // 104,448 B
#define W_U4 (128 * LDS_ * 2 / 16)

__global__ __launch_bounds__(256, 2) void gemm_mma_kernel(
    const float* __restrict__ X,
    const ushort* __restrict__ Whi, const ushort* __restrict__ Wlo,
    float* __restrict__ Y, int n)
{
    extern __shared__ char sm[];
    const int t   = threadIdx.x;
    const int lid = t & 31;
    const int wid = t >> 5;
    const int row0 = blockIdx.x * 64;

    {
        const uint4* wh4 = (const uint4*)Whi;
        const uint4* wl4 = (const uint4*)Wlo;
        uint4* dh = (uint4*)(sm + OFF_WH);
        uint4* dl = (uint4*)(sm + OFF_WL);
        for (int i = t; i < W_U4; i += 256) {
            dh[i] = __ldg(wh4 + i);
            dl[i] = __ldg(wl4 + i);
        }
    }

    for (int i = t; i < 64 * 32; i += 256) {
        int m = i >> 5, q = i & 31;
        int r = row0 + m;
        int rc = r < n ? r : 0;
        float4 v = __ldg((const float4*)(X + (size_t)rc * HID) + q);
        float f[4] = {v.x, v.y, v.z, v.w};
        ushort h[4], l[4];
#pragma unroll
        for (int j = 0; j < 4; j++) split2(f[j], h[j], l[j]);
        uint2 hp = make_uint2((uint32_t)h[0] | ((uint32_t)h[1] << 16),
                              (uint32_t)h[2] | ((uint32_t)h[3] << 16));
        uint2 lp = make_uint2((uint32_t)l[0] | ((uint32_t)l[1] << 16),
                              (uint32_t)l[2] | ((uint32_t)l[3] << 16));
        size_t off = ((size_t)m * LDS_ + q * 4) * 2;
        *(uint2*)(sm + OFF_XH + off) = hp;
        *(uint2*)(sm + OFF_XL + off) = lp;
    }
    __syncthreads();

    const int wm = wid & 1;
    const int wn = wid >> 1;
    const int mat  = lid >> 3;
    const int rsel = (mat & 1) * 8 + (lid & 7);
    const int csel = (mat >> 1) * 8;

    const uint32_t sb = smem_u32(sm);
    uint32_t aH = sb + OFF_XH + (uint32_t)(((wm * 32 + rsel) * LDS_ + csel) * 2);
    uint32_t aL = aH + (OFF_XL - OFF_XH);
    uint32_t bH = sb + OFF_WH + (uint32_t)((rsel * LDS_ + wn * 32 + csel) * 2);
    uint32_t bL = bH + (OFF_WL - OFF_WH);

    float acc[2][4][4];
#pragma unroll
    for (int mi = 0; mi < 2; mi++)
#pragma unroll
        for (int nj = 0; nj < 4; nj++)
#pragma unroll
            for (int e = 0; e < 4; e++) acc[mi][nj][e] = 0.f;

#pragma unroll
    for (int ks = 0; ks < 8; ks++) {
        const uint32_t ao = ks * 32;
        const uint32_t bo = (uint32_t)(ks * 16 * LDS_ * 2);

        uint32_t ah[2][4], al[2][4];
        LDM_X4(ah[0][0], ah[0][1], ah[0][2], ah[0][3], aH + ao);
        LDM_X4(ah[1][0], ah[1][1], ah[1][2], ah[1][3], aH + ao + 16 * LDS_ * 2);
        LDM_X4(al[0][0], al[0][1], al[0][2], al[0][3], aL + ao);
        LDM_X4(al[1][0], al[1][1], al[1][2], al[1][3], aL + ao + 16 * LDS_ * 2);

        uint32_t bh[4][2], bl[4][2];
#pragma unroll
        for (int g = 0; g < 2; g++) {
            LDM_X4T(bh[g * 2][0], bh[g * 2][1], bh[g * 2 + 1][0], bh[g * 2 + 1][1],
                    bH + bo + g * 32);
            LDM_X4T(bl[g * 2][0], bl[g * 2][1], bl[g * 2 + 1][0], bl[g * 2 + 1][1],
                    bL + bo + g * 32);
        }

#pragma unroll
        for (int mi = 0; mi < 2; mi++)
#pragma unroll
            for (int nj = 0; nj < 4; nj++) {
                MMA_BF16(acc[mi][nj], ah[mi], bh[nj]);
                MMA_BF16(acc[mi][nj], ah[mi], bl[nj]);
                MMA_BF16(acc[mi][nj], al[mi], bh[nj]);
            }
    }

    const int g  = lid >> 2;
    const int c2 = (lid & 3) * 2;
#pragma unroll
    for (int mi = 0; mi < 2; mi++) {
        int rbase = row0 + wm * 32 + mi * 16;
        int r1 = rbase + g, r2 = rbase + g + 8;
#pragma unroll
        for (int nj = 0; nj < 4; nj++) {
            int col = wn * 32 + nj * 8 + c2;
            if (r1 < n)
                *(float2*)(Y + (size_t)r1 * HID + col) =
                    make_float2(acc[mi][nj][0], acc[mi][nj][1]);
            if (r2 < n)
                *(float2*)(Y + (size_t)r2 * HID + col) =
                    make_float2(acc[mi][nj][2], acc[mi][nj][3]);
        }
    }
}

// ---------------------------------------------------------------------------
// Fused CSR scatter + projection: one warp per dst node.
//   acc = sum_{edges->node} w * xw1[src]   (registers, no atomics)
//   y2[node] = relu(acc) @ V ; c[node] = 0
// ---------------------------------------------------------------------------
__global__ __launch_bounds__(256) void scatter_csr_fused_kernel(
    const float* __restrict__ F, const int* __restrict__ off,
    const int* __restrict__ cnt, const int2* __restrict__ epk,
    const float* __restrict__ VT,
    float* __restrict__ y2, float* __restrict__ c, int n)
{
    int node = (int)(((long long)blockIdx.x * blockDim.x + threadIdx.x) >> 5);
    int lane = threadIdx.x & 31;
    if (node >= n) return;

    float4 vv[4];
#pragma unroll
    for (int j = 0; j < 4; j++)
        vv[j] = __ldg((const float4*)(VT + j * HID) + lane);

    int b = __ldg(off + node);
    int e = b + __ldg(cnt + node);

    float4 acc = make_float4(0.f, 0.f, 0.f, 0.f);
    int i = b;
    for (; i + 4 <= e; i += 4) {
        int2 e0 = __ldg(epk + i),     e1 = __ldg(epk + i + 1);
        int2 e2 = __ldg(epk + i + 2), e3 = __ldg(epk + i + 3);
        float4 v0 = __ldg((const float4*)(F + (size_t)e0.x * HID) + lane);
        float4 v1 = __ldg((const float4*)(F + (size_t)e1.x * HID) + lane);
        float4 v2 = __ldg((const float4*)(F + (size_t)e2.x * HID) + lane);
        float4 v3 = __ldg((const float4*)(F + (size_t)e3.x * HID) + lane);
        float w0 = __int_as_float(e0.y), w1 = __int_as_float(e1.y);
        float w2 = __int_as_float(e2.y), w3 = __int_as_float(e3.y);
        acc.x = fmaf(w0, v0.x, fmaf(w1, v1.x, fmaf(w2, v2.x, fmaf(w3, v3.x, acc.x))));
        acc.y = fmaf(w0, v0.y, fmaf(w1, v1.y, fmaf(w2, v2.y, fmaf(w3, v3.y, acc.y))));
        acc.z = fmaf(w0, v0.z, fmaf(w1, v1.z, fmaf(w2, v2.z, fmaf(w3, v3.z, acc.z))));
        acc.w = fmaf(w0, v0.w, fmaf(w1, v1.w, fmaf(w2, v2.w, fmaf(w3, v3.w, acc.w))));
    }
    for (; i < e; i++) {
        int2 ed = __ldg(epk + i);
        float w = __int_as_float(ed.y);
        float4 v = __ldg((const float4*)(F + (size_t)ed.x * HID) + lane);
        acc.x = fmaf(w, v.x, acc.x); acc.y = fmaf(w, v.y, acc.y);
        acc.z = fmaf(w, v.z, acc.z); acc.w = fmaf(w, v.w, acc.w);
    }

    float rx = fmaxf(acc.x, 0.f), ry = fmaxf(acc.y, 0.f);
    float rz = fmaxf(acc.z, 0.f), rw = fmaxf(acc.w, 0.f);
    float d[4];
#pragma unroll
    for (int j = 0; j < 4; j++)
        d[j] = rx * vv[j].x + ry * vv[j].y + rz * vv[j].z + rw * vv[j].w;
#pragma unroll
    for (int o = 16; o > 0; o >>= 1) {
#pragma unroll
        for (int j = 0; j < 4; j++)
            d[j] += __shfl_xor_sync(0xFFFFFFFFu, d[j], o);
    }
    if (lane == 0) {
        ((float4*)y2)[node] = make_float4(d[0], d[1], d[2], d[3]);
        ((float4*)c)[node]  = make_float4(0.f, 0.f, 0.f, 0.f);
    }
}

// ---------------------------------------------------------------------------
// Narrow scatter (layer 2 collapsed): c[dst] += w_e * y2[src]. 4 edges/thread.
// ---------------------------------------------------------------------------
__global__ __launch_bounds__(256) void scatter4_kernel(
    const float* __restrict__ y2, const int* __restrict__ ei,
    const float* __restrict__ ew, float* __restrict__ c, int E)
{
    int tI = blockIdx.x * blockDim.x + threadIdx.x;
    int e0 = tI * 4;
    if (e0 >= E) return;

    if (e0 + 4 <= E) {
        int4   s4 = __ldg((const int4*)ei + tI);
        int4   d4 = __ldg((const int4*)(ei + E) + tI);
        float4 w4 = __ldg((const float4*)ew + tI);
        int   s[4] = {s4.x, s4.y, s4.z, s4.w};
        int   d[4] = {d4.x, d4.y, d4.z, d4.w};
        float w[4] = {w4.x, w4.y, w4.z, w4.w};
        float4 v[4];
#pragma unroll
        for (int j = 0; j < 4; j++) v[j] = __ldg((const float4*)y2 + s[j]);
#pragma unroll
        for (int j = 0; j < 4; j++) {
            v[j].x *= w[j]; v[j].y *= w[j]; v[j].z *= w[j]; v[j].w *= w[j];
            float* p = c + (size_t)d[j] * 4;
            asm volatile("red.global.add.v4.f32 [%0], {%1,%2,%3,%4};"
                         :: "l"(p), "f"(v[j].x), "f"(v[j].y), "f"(v[j].z), "f"(v[j].w)
                         : "memory");
        }
    } else {
        for (int e = e0; e < E; e++) {
            int   s = __ldg(ei + e);
            int   d = __ldg(ei + E + e);
            float w = __ldg(ew + e);
            float4 v = __ldg((const float4*)y2 + s);
            v.x *= w; v.y *= w; v.z *= w; v.w *= w;
            float* p = c + (size_t)d * 4;
            asm volatile("red.global.add.v4.f32 [%0], {%1,%2,%3,%4};"
                         :: "l"(p), "f"(v.x), "f"(v.y), "f"(v.z), "f"(v.w) : "memory");
        }
    }
}

// ---------------------------------------------------------------------------
// Pair epilogue: out[p] = (c[a].0 + c[b].1, c[a].2 + c[b].3)
// ---------------------------------------------------------------------------
__global__ __launch_bounds__(256) void pair_small_kernel(
    const float* __restrict__ c, const int* __restrict__ pe,
    float* __restrict__ out, int P)
{
    int p = blockIdx.x * blockDim.x + threadIdx.x;
    if (p >= P) return;
    int a = __ldg(pe + p);
    int b = __ldg(pe + P + p);
    float4 ca = __ldg((const float4*)c + a);
    float4 cb = __ldg((const float4*)c + b);
    ((float2*)out)[p] = make_float2(ca.x + cb.y, ca.z + cb.w);
}

// ---------------------------------------------------------------------------
// Launch
// ---------------------------------------------------------------------------
extern "C" void kernel_launch(void* const* d_in, const int* in_sizes, int n_in,
                              void* d_out, int out_size)
{
    const float* x    = (const float*)d_in[0];
    const int*   ei1  = (const int*)  d_in[1];
    const int*   ei2  = (const int*)  d_in[2];
    const float* ew1  = (const float*)d_in[3];
    const float* ew2  = (const float*)d_in[4];
    const int*   pe   = (const int*)  d_in[5];
    const float* W1   = (const float*)d_in[6];
    const float* W2   = (const float*)d_in[7];
    const float* Wlin = (const float*)d_in[8];
    float* out = (float*)d_out;

    int n  = in_sizes[0] / HID;
    int E1 = in_sizes[3];
    int E2 = in_sizes[4];
    int P  = in_sizes[5] / 2;

    void *p_buf0, *p_y2, *p_c, *p_VT, *p_Whi, *p_Wlo;
    void *p_cnt, *p_off, *p_cur, *p_tot, *p_epk;
    cudaGetSymbolAddress(&p_buf0, g_buf0);
    cudaGetSymbolAddress(&p_y2,   g_y2);
    cudaGetSymbolAddress(&p_c,    g_c);
    cudaGetSymbolAddress(&p_VT,   g_VT);
    cudaGetSymbolAddress(&p_Whi,  g_Whi);
    cudaGetSymbolAddress(&p_Wlo,  g_Wlo);
    cudaGetSymbolAddress(&p_cnt,  g_cnt);
    cudaGetSymbolAddress(&p_off,  g_off);
    cudaGetSymbolAddress(&p_cur,  g_cur);
    cudaGetSymbolAddress(&p_tot,  g_tot);
    cudaGetSymbolAddress(&p_epk,  g_epk);
    float*  buf0 = (float*)p_buf0;
    float*  y2   = (float*)p_y2;
    float*  c    = (float*)p_c;
    float*  VT   = (float*)p_VT;
    ushort* Whi  = (ushort*)p_Whi;
    ushort* Wlo  = (ushort*)p_Wlo;
    int*    cnt  = (int*)p_cnt;
    int*    off  = (int*)p_off;
    int*    cur  = (int*)p_cur;
    int*    tot  = (int*)p_tot;
    int2*   epk  = (int2*)p_epk;

    cudaFuncSetAttribute(gemm_mma_kernel,
        cudaFuncAttributeMaxDynamicSharedMemorySize, GEMM_SMEM_BYTES);

    // Precomputes
    wsplit_kernel<<<16, 256>>>(W1, Whi, Wlo);
    vpack_kernel<<<1, 512>>>(W2, Wlin, VT);

    // CSR build for edge set 1 (dst-grouped; placement via warp-agg alloc)
    cudaMemsetAsync(cnt, 0, (size_t)n * sizeof(int));
    cudaMemsetAsync(tot, 0, sizeof(int));
    {
        int q = (E1 + 3) / 4;
        hist_kernel<<<(q + 255) / 256, 256>>>(ei1, E1, cnt);
        alloc_kernel<<<(n + 255) / 256, 256>>>(cnt, off, cur, tot, n);
        reorder_kernel<<<(q + 255) / 256, 256>>>(ei1, ew1, E1, cur, epk);
    }

    // GEMM1: buf0 = x @ W1
    int gemmBlocks = (n + 63) / 64;
    gemm_mma_kernel<<<gemmBlocks, 256, GEMM_SMEM_BYTES>>>(x, Whi, Wlo, buf0, n);

    // Fused CSR aggregate + relu + V projection (writes y2, zeroes c)
    {
        long long th = (long long)n * 32;
        scatter_csr_fused_kernel<<<(int)((th + 255) / 256), 256>>>(
            buf0, off, cnt, epk, VT, y2, c, n);
    }

    // Narrow scatter (layer 2 collapsed)
    {
        int threads = (E2 + 3) / 4;
        scatter4_kernel<<<(threads + 255) / 256, 256>>>(y2, ei2, ew2, c, E2);
    }

    // Pair epilogue
    pair_small_kernel<<<(P + 255) / 256, 256>>>(c, pe, out, P);
}

// round 11
// speedup vs baseline: 1.8556x; 1.0618x over previous
#include <cuda_runtime.h>
#include <cuda_bf16.h>
#include <cstdint>

#define HID 128
#define NMAX 100000
#define EMAX 800000

__device__ float  g_buf0[(size_t)NMAX * HID];  // xw1
__device__ float  g_y2  [(size_t)NMAX * 4];    // relu(h) @ V
__device__ float  g_c   [(size_t)NMAX * 4];    // layer-2 collapsed aggregate
__device__ float  g_VT  [4 * HID];             // (W2 @ WlinPacked)^T : VT[j][k]
__device__ ushort g_Whi [128 * 136];           // W1 hi, padded [k][n] layout
__device__ ushort g_Wlo [128 * 136];           // W1 lo
__device__ int    g_cnt [NMAX];                // CSR degree
__device__ int    g_off [NMAX];                // CSR segment starts
__device__ int    g_cur [NMAX];                // CSR fill cursors
__device__ int    g_tot [1];                   // allocation counter
__device__ int2   g_epk [EMAX];                // CSR edges: {src, w bits}

__device__ __forceinline__ uint32_t smem_u32(const void* p) {
    uint32_t a;
    asm("{ .reg .u64 t; cvta.to.shared.u64 t, %1; cvt.u32.u64 %0, t; }"
        : "=r"(a) : "l"(p));
    return a;
}

#define LDM_X4(r0, r1, r2, r3, a)                                             \
    asm volatile("ldmatrix.sync.aligned.m8n8.x4.shared.b16 {%0,%1,%2,%3}, [%4];" \
                 : "=r"(r0), "=r"(r1), "=r"(r2), "=r"(r3) : "r"(a))
#define LDM_X4T(r0, r1, r2, r3, a)                                            \
    asm volatile("ldmatrix.sync.aligned.m8n8.x4.trans.shared.b16 {%0,%1,%2,%3}, [%4];" \
                 : "=r"(r0), "=r"(r1), "=r"(r2), "=r"(r3) : "r"(a))
#define MMA_BF16(d, a, b)                                                     \
    asm volatile("mma.sync.aligned.m16n8k16.row.col.f32.bf16.bf16.f32 "       \
                 "{%0,%1,%2,%3}, {%4,%5,%6,%7}, {%8,%9}, {%0,%1,%2,%3};"      \
                 : "+f"((d)[0]), "+f"((d)[1]), "+f"((d)[2]), "+f"((d)[3])     \
                 : "r"((a)[0]), "r"((a)[1]), "r"((a)[2]), "r"((a)[3]),        \
                   "r"((b)[0]), "r"((b)[1]))

__device__ __forceinline__ void split2(float f, ushort& h, ushort& l) {
    uint32_t fb = __float_as_uint(f);
    h = (ushort)(fb >> 16);
    float lo = f - __uint_as_float(fb & 0xFFFF0000u);   // exact
    __nv_bfloat16 bl = __float2bfloat16_rn(lo);
    l = *(ushort*)&bl;
}

// ---------------------------------------------------------------------------
// Pre-split W1 into bf16 hi/lo, padded [k][136] layout.
// ---------------------------------------------------------------------------
__global__ void wsplit_kernel(const float* __restrict__ W,
                              ushort* __restrict__ Whi, ushort* __restrict__ Wlo)
{
    int i = blockIdx.x * blockDim.x + threadIdx.x;
    if (i >= 128 * 32) return;
    int k = i >> 5, q = i & 31;
    float4 v = __ldg((const float4*)(W + (size_t)k * HID) + q);
    float f[4] = {v.x, v.y, v.z, v.w};
    ushort h[4], l[4];
#pragma unroll
    for (int j = 0; j < 4; j++) split2(f[j], h[j], l[j]);
    uint2 hp = make_uint2((uint32_t)h[0] | ((uint32_t)h[1] << 16),
                          (uint32_t)h[2] | ((uint32_t)h[3] << 16));
    uint2 lp = make_uint2((uint32_t)l[0] | ((uint32_t)l[1] << 16),
                          (uint32_t)l[2] | ((uint32_t)l[3] << 16));
    *(uint2*)(Whi + (size_t)k * 136 + q * 4) = hp;
    *(uint2*)(Wlo + (size_t)k * 136 + q * 4) = lp;
}

// ---------------------------------------------------------------------------
// VT[j][k] = sum_c W2[k,c] * wl_j[c]
// ---------------------------------------------------------------------------
__global__ void vpack_kernel(const float* __restrict__ W2,
                             const float* __restrict__ Wlin,
                             float* __restrict__ VT)
{
    int i = threadIdx.x;          // 0..511
    int k = i >> 2, j = i & 3;
    const float* wl = Wlin + (j >> 1) * 256 + (j & 1) * 128;
    const float* wr = W2 + (size_t)k * HID;
    float acc = 0.f;
#pragma unroll 8
    for (int c = 0; c < HID; c++) acc += __ldg(wr + c) * __ldg(wl + c);
    VT[j * HID + k] = acc;
}

// ---------------------------------------------------------------------------
// CSR build: histogram -> warp-aggregated segment allocation -> reorder
// ---------------------------------------------------------------------------
__global__ void hist_kernel(const int* __restrict__ ei, int E, int* __restrict__ cnt)
{
    int i = blockIdx.x * blockDim.x + threadIdx.x;
    int e0 = i * 4;
    if (e0 >= E) return;
    if (e0 + 4 <= E) {
        int4 d = __ldg((const int4*)(ei + E) + i);
        atomicAdd(&cnt[d.x], 1); atomicAdd(&cnt[d.y], 1);
        atomicAdd(&cnt[d.z], 1); atomicAdd(&cnt[d.w], 1);
    } else {
        for (int e = e0; e < E; e++) atomicAdd(&cnt[__ldg(ei + E + e)], 1);
    }
}

// Warp inclusive scan of degrees, one atomicAdd per warp for segment base.
__global__ __launch_bounds__(256) void alloc_kernel(
    const int* __restrict__ cnt, int* __restrict__ off, int* __restrict__ cur,
    int* __restrict__ total, int n)
{
    int i = blockIdx.x * blockDim.x + threadIdx.x;
    int lane = threadIdx.x & 31;
    int cv = (i < n) ? __ldg(cnt + i) : 0;
    int sc = cv;
#pragma unroll
    for (int o = 1; o < 32; o <<= 1) {
        int v = __shfl_up_sync(0xFFFFFFFFu, sc, o);
        if (lane >= o) sc += v;
    }
    int wsum = __shfl_sync(0xFFFFFFFFu, sc, 31);
    int base = 0;
    if (lane == 31 && wsum > 0) base = atomicAdd(total, wsum);
    base = __shfl_sync(0xFFFFFFFFu, base, 31);
    if (i < n) {
        int o = base + sc - cv;
        off[i] = o; cur[i] = o;
    }
}

__global__ void reorder_kernel(const int* __restrict__ ei,
                               const float* __restrict__ ew, int E,
                               int* __restrict__ cur, int2* __restrict__ epk)
{
    int i = blockIdx.x * blockDim.x + threadIdx.x;
    int e0 = i * 4;
    if (e0 >= E) return;
    if (e0 + 4 <= E) {
        int4   s4 = __ldg((const int4*)ei + i);
        int4   d4 = __ldg((const int4*)(ei + E) + i);
        float4 w4 = __ldg((const float4*)ew + i);
        int   s[4] = {s4.x, s4.y, s4.z, s4.w};
        int   d[4] = {d4.x, d4.y, d4.z, d4.w};
        float w[4] = {w4.x, w4.y, w4.z, w4.w};
#pragma unroll
        for (int j = 0; j < 4; j++) {
            int pos = atomicAdd(&cur[d[j]], 1);
            epk[pos] = make_int2(s[j], __float_as_int(w[j]));
        }
    } else {
        for (int e = e0; e < E; e++) {
            int pos = atomicAdd(&cur[__ldg(ei + E + e)], 1);
            epk[pos] = make_int2(__ldg(ei + e), __float_as_int(__ldg(ew + e)));
        }
    }
}

// ===========================================================================
// GEMM1 (HMMA bf16x3): Y[n,128] = X @ W1. Pre-split W; no zero pass.
// ===========================================================================
#define LDS_ 136
#define OFF_XH 0
#define OFF_XL (64 * LDS_ * 2)
#define OFF_WH (2 * 64 * LDS_ * 2)
#define OFF_WL (OFF_WH + 128 * LDS_ * 2)
#define GEMM_SMEM_BYTES (OFF_WL + 128 * LDS_ * 2)   // 104,448 B
#define W_U4 (128 * LDS_ * 2 / 16)

__global__ __launch_bounds__(256, 2) void gemm_mma_kernel(
    const float* __restrict__ X,
    const ushort* __restrict__ Whi, const ushort* __restrict__ Wlo,
    float* __restrict__ Y, int n)
{
    extern __shared__ char sm[];
    const int t   = threadIdx.x;
    const int lid = t & 31;
    const int wid = t >> 5;
    const int row0 = blockIdx.x * 64;

    {
        const uint4* wh4 = (const uint4*)Whi;
        const uint4* wl4 = (const uint4*)Wlo;
        uint4* dh = (uint4*)(sm + OFF_WH);
        uint4* dl = (uint4*)(sm + OFF_WL);
        for (int i = t; i < W_U4; i += 256) {
            dh[i] = __ldg(wh4 + i);
            dl[i] = __ldg(wl4 + i);
        }
    }

    for (int i = t; i < 64 * 32; i += 256) {
        int m = i >> 5, q = i & 31;
        int r = row0 + m;
        int rc = r < n ? r : 0;
        float4 v = __ldg((const float4*)(X + (size_t)rc * HID) + q);
        float f[4] = {v.x, v.y, v.z, v.w};
        ushort h[4], l[4];
#pragma unroll
        for (int j = 0; j < 4; j++) split2(f[j], h[j], l[j]);
        uint2 hp = make_uint2((uint32_t)h[0] | ((uint32_t)h[1] << 16),
                              (uint32_t)h[2] | ((uint32_t)h[3] << 16));
        uint2 lp = make_uint2((uint32_t)l[0] | ((uint32_t)l[1] << 16),
                              (uint32_t)l[2] | ((uint32_t)l[3] << 16));
        size_t off = ((size_t)m * LDS_ + q * 4) * 2;
        *(uint2*)(sm + OFF_XH + off) = hp;
        *(uint2*)(sm + OFF_XL + off) = lp;
    }
    __syncthreads();

    const int wm = wid & 1;
    const int wn = wid >> 1;
    const int mat  = lid >> 3;
    const int rsel = (mat & 1) * 8 + (lid & 7);
    const int csel = (mat >> 1) * 8;

    const uint32_t sb = smem_u32(sm);
    uint32_t aH = sb + OFF_XH + (uint32_t)(((wm * 32 + rsel) * LDS_ + csel) * 2);
    uint32_t aL = aH + (OFF_XL - OFF_XH);
    uint32_t bH = sb + OFF_WH + (uint32_t)((rsel * LDS_ + wn * 32 + csel) * 2);
    uint32_t bL = bH + (OFF_WL - OFF_WH);

    float acc[2][4][4];
#pragma unroll
    for (int mi = 0; mi < 2; mi++)
#pragma unroll
        for (int nj = 0; nj < 4; nj++)
#pragma unroll
            for (int e = 0; e < 4; e++) acc[mi][nj][e] = 0.f;

#pragma unroll
    for (int ks = 0; ks < 8; ks++) {
        const uint32_t ao = ks * 32;
        const uint32_t bo = (uint32_t)(ks * 16 * LDS_ * 2);

        uint32_t ah[2][4], al[2][4];
        LDM_X4(ah[0][0], ah[0][1], ah[0][2], ah[0][3], aH + ao);
        LDM_X4(ah[1][0], ah[1][1], ah[1][2], ah[1][3], aH + ao + 16 * LDS_ * 2);
        LDM_X4(al[0][0], al[0][1], al[0][2], al[0][3], aL + ao);
        LDM_X4(al[1][0], al[1][1], al[1][2], al[1][3], aL + ao + 16 * LDS_ * 2);

        uint32_t bh[4][2], bl[4][2];
#pragma unroll
        for (int g = 0; g < 2; g++) {
            LDM_X4T(bh[g * 2][0], bh[g * 2][1], bh[g * 2 + 1][0], bh[g * 2 + 1][1],
                    bH + bo + g * 32);
            LDM_X4T(bl[g * 2][0], bl[g * 2][1], bl[g * 2 + 1][0], bl[g * 2 + 1][1],
                    bL + bo + g * 32);
        }

#pragma unroll
        for (int mi = 0; mi < 2; mi++)
#pragma unroll
            for (int nj = 0; nj < 4; nj++) {
                MMA_BF16(acc[mi][nj], ah[mi], bh[nj]);
                MMA_BF16(acc[mi][nj], ah[mi], bl[nj]);
                MMA_BF16(acc[mi][nj], al[mi], bh[nj]);
            }
    }

    const int g  = lid >> 2;
    const int c2 = (lid & 3) * 2;
#pragma unroll
    for (int mi = 0; mi < 2; mi++) {
        int rbase = row0 + wm * 32 + mi * 16;
        int r1 = rbase + g, r2 = rbase + g + 8;
#pragma unroll
        for (int nj = 0; nj < 4; nj++) {
            int col = wn * 32 + nj * 8 + c2;
            if (r1 < n)
                *(float2*)(Y + (size_t)r1 * HID + col) =
                    make_float2(acc[mi][nj][0], acc[mi][nj][1]);
            if (r2 < n)
                *(float2*)(Y + (size_t)r2 * HID + col) =
                    make_float2(acc[mi][nj][2], acc[mi][nj][3]);
        }
    }
}

// ---------------------------------------------------------------------------
// Fused CSR scatter + projection: one warp per dst node.
// ---------------------------------------------------------------------------
__global__ __launch_bounds__(256) void scatter_csr_fused_kernel(
    const float* __restrict__ F, const int* __restrict__ off,
    const int* __restrict__ cnt, const int2* __restrict__ epk,
    const float* __restrict__ VT,
    float* __restrict__ y2, float* __restrict__ c, int n)
{
    int node = (int)(((long long)blockIdx.x * blockDim.x + threadIdx.x) >> 5);
    int lane = threadIdx.x & 31;
    if (node >= n) return;

    float4 vv[4];
#pragma unroll
    for (int j = 0; j < 4; j++)
        vv[j] = __ldg((const float4*)(VT + j * HID) + lane);

    int b = __ldg(off + node);
    int e = b + __ldg(cnt + node);

    float4 acc = make_float4(0.f, 0.f, 0.f, 0.f);
    int i = b;
    for (; i + 4 <= e; i += 4) {
        int2 e0 = __ldg(epk + i),     e1 = __ldg(epk + i + 1);
        int2 e2 = __ldg(epk + i + 2), e3 = __ldg(epk + i + 3);
        float4 v0 = __ldg((const float4*)(F + (size_t)e0.x * HID) + lane);
        float4 v1 = __ldg((const float4*)(F + (size_t)e1.x * HID) + lane);
        float4 v2 = __ldg((const float4*)(F + (size_t)e2.x * HID) + lane);
        float4 v3 = __ldg((const float4*)(F + (size_t)e3.x * HID) + lane);
        float w0 = __int_as_float(e0.y), w1 = __int_as_float(e1.y);
        float w2 = __int_as_float(e2.y), w3 = __int_as_float(e3.y);
        acc.x = fmaf(w0, v0.x, fmaf(w1, v1.x, fmaf(w2, v2.x, fmaf(w3, v3.x, acc.x))));
        acc.y = fmaf(w0, v0.y, fmaf(w1, v1.y, fmaf(w2, v2.y, fmaf(w3, v3.y, acc.y))));
        acc.z = fmaf(w0, v0.z, fmaf(w1, v1.z, fmaf(w2, v2.z, fmaf(w3, v3.z, acc.z))));
        acc.w = fmaf(w0, v0.w, fmaf(w1, v1.w, fmaf(w2, v2.w, fmaf(w3, v3.w, acc.w))));
    }
    for (; i < e; i++) {
        int2 ed = __ldg(epk + i);
        float w = __int_as_float(ed.y);
        float4 v = __ldg((const float4*)(F + (size_t)ed.x * HID) + lane);
        acc.x = fmaf(w, v.x, acc.x); acc.y = fmaf(w, v.y, acc.y);
        acc.z = fmaf(w, v.z, acc.z); acc.w = fmaf(w, v.w, acc.w);
    }

    float rx = fmaxf(acc.x, 0.f), ry = fmaxf(acc.y, 0.f);
    float rz = fmaxf(acc.z, 0.f), rw = fmaxf(acc.w, 0.f);
    float d[4];
#pragma unroll
    for (int j = 0; j < 4; j++)
        d[j] = rx * vv[j].x + ry * vv[j].y + rz * vv[j].z + rw * vv[j].w;
#pragma unroll
    for (int o = 16; o > 0; o >>= 1) {
#pragma unroll
        for (int j = 0; j < 4; j++)
            d[j] += __shfl_xor_sync(0xFFFFFFFFu, d[j], o);
    }
    if (lane == 0) {
        ((float4*)y2)[node] = make_float4(d[0], d[1], d[2], d[3]);
        ((float4*)c)[node]  = make_float4(0.f, 0.f, 0.f, 0.f);
    }
}

// ---------------------------------------------------------------------------
// Narrow scatter (layer 2 collapsed): c[dst] += w_e * y2[src]. 4 edges/thread.
// ---------------------------------------------------------------------------
__global__ __launch_bounds__(256) void scatter4_kernel(
    const float* __restrict__ y2, const int* __restrict__ ei,
    const float* __restrict__ ew, float* __restrict__ c, int E)
{
    int tI = blockIdx.x * blockDim.x + threadIdx.x;
    int e0 = tI * 4;
    if (e0 >= E) return;

    if (e0 + 4 <= E) {
        int4   s4 = __ldg((const int4*)ei + tI);
        int4   d4 = __ldg((const int4*)(ei + E) + tI);
        float4 w4 = __ldg((const float4*)ew + tI);
        int   s[4] = {s4.x, s4.y, s4.z, s4.w};
        int   d[4] = {d4.x, d4.y, d4.z, d4.w};
        float w[4] = {w4.x, w4.y, w4.z, w4.w};
        float4 v[4];
#pragma unroll
        for (int j = 0; j < 4; j++) v[j] = __ldg((const float4*)y2 + s[j]);
#pragma unroll
        for (int j = 0; j < 4; j++) {
            v[j].x *= w[j]; v[j].y *= w[j]; v[j].z *= w[j]; v[j].w *= w[j];
            float* p = c + (size_t)d[j] * 4;
            asm volatile("red.global.add.v4.f32 [%0], {%1,%2,%3,%4};"
                         :: "l"(p), "f"(v[j].x), "f"(v[j].y), "f"(v[j].z), "f"(v[j].w)
                         : "memory");
        }
    } else {
        for (int e = e0; e < E; e++) {
            int   s = __ldg(ei + e);
            int   d = __ldg(ei + E + e);
            float w = __ldg(ew + e);
            float4 v = __ldg((const float4*)y2 + s);
            v.x *= w; v.y *= w; v.z *= w; v.w *= w;
            float* p = c + (size_t)d * 4;
            asm volatile("red.global.add.v4.f32 [%0], {%1,%2,%3,%4};"
                         :: "l"(p), "f"(v.x), "f"(v.y), "f"(v.z), "f"(v.w) : "memory");
        }
    }
}

// ---------------------------------------------------------------------------
// Pair epilogue: out[p] = (c[a].0 + c[b].1, c[a].2 + c[b].3)
// ---------------------------------------------------------------------------
__global__ __launch_bounds__(256) void pair_small_kernel(
    const float* __restrict__ c, const int* __restrict__ pe,
    float* __restrict__ out, int P)
{
    int p = blockIdx.x * blockDim.x + threadIdx.x;
    if (p >= P) return;
    int a = __ldg(pe + p);
    int b = __ldg(pe + P + p);
    float4 ca = __ldg((const float4*)c + a);
    float4 cb = __ldg((const float4*)c + b);
    ((float2*)out)[p] = make_float2(ca.x + cb.y, ca.z + cb.w);
}

// ---------------------------------------------------------------------------
// Launch: stream-fork so CSR build overlaps the GEMM.
// Stream/events created once on the first (eager) call; capture reuses them.
// ---------------------------------------------------------------------------
extern "C" void kernel_launch(void* const* d_in, const int* in_sizes, int n_in,
                              void* d_out, int out_size)
{
    const float* x    = (const float*)d_in[0];
    const int*   ei1  = (const int*)  d_in[1];
    const int*   ei2  = (const int*)  d_in[2];
    const float* ew1  = (const float*)d_in[3];
    const float* ew2  = (const float*)d_in[4];
    const int*   pe   = (const int*)  d_in[5];
    const float* W1   = (const float*)d_in[6];
    const float* W2   = (const float*)d_in[7];
    const float* Wlin = (const float*)d_in[8];
    float* out = (float*)d_out;

    int n  = in_sizes[0] / HID;
    int E1 = in_sizes[3];
    int E2 = in_sizes[4];
    int P  = in_sizes[5] / 2;

    void *p_buf0, *p_y2, *p_c, *p_VT, *p_Whi, *p_Wlo;
    void *p_cnt, *p_off, *p_cur, *p_tot, *p_epk;
    cudaGetSymbolAddress(&p_buf0, g_buf0);
    cudaGetSymbolAddress(&p_y2,   g_y2);
    cudaGetSymbolAddress(&p_c,    g_c);
    cudaGetSymbolAddress(&p_VT,   g_VT);
    cudaGetSymbolAddress(&p_Whi,  g_Whi);
    cudaGetSymbolAddress(&p_Wlo,  g_Wlo);
    cudaGetSymbolAddress(&p_cnt,  g_cnt);
    cudaGetSymbolAddress(&p_off,  g_off);
    cudaGetSymbolAddress(&p_cur,  g_cur);
    cudaGetSymbolAddress(&p_tot,  g_tot);
    cudaGetSymbolAddress(&p_epk,  g_epk);
    float*  buf0 = (float*)p_buf0;
    float*  y2   = (float*)p_y2;
    float*  c    = (float*)p_c;
    float*  VT   = (float*)p_VT;
    ushort* Whi  = (ushort*)p_Whi;
    ushort* Wlo  = (ushort*)p_Wlo;
    int*    cnt  = (int*)p_cnt;
    int*    off  = (int*)p_off;
    int*    cur  = (int*)p_cur;
    int*    tot  = (int*)p_tot;
    int2*   epk  = (int2*)p_epk;

    cudaFuncSetAttribute(gemm_mma_kernel,
        cudaFuncAttributeMaxDynamicSharedMemorySize, GEMM_SMEM_BYTES);

    // One-time side stream + fork/join events (created on eager first call,
    // reused during capture — no creation APIs run while capturing).
    static cudaStream_t s1 = nullptr;
    static cudaEvent_t evFork = nullptr, evJoin = nullptr;
    if (s1 == nullptr) {
        cudaStreamCreateWithFlags(&s1, cudaStreamNonBlocking);
        cudaEventCreateWithFlags(&evFork, cudaEventDisableTiming);
        cudaEventCreateWithFlags(&evJoin, cudaEventDisableTiming);
    }

    // ---- fork: side stream does CSR build + vpack
    cudaEventRecord(evFork, 0);
    cudaStreamWaitEvent(s1, evFork, 0);

    cudaMemsetAsync(cnt, 0, (size_t)n * sizeof(int), s1);
    cudaMemsetAsync(tot, 0, sizeof(int), s1);
    {
        int q = (E1 + 3) / 4;
        hist_kernel<<<(q + 255) / 256, 256, 0, s1>>>(ei1, E1, cnt);
        alloc_kernel<<<(n + 255) / 256, 256, 0, s1>>>(cnt, off, cur, tot, n);
        reorder_kernel<<<(q + 255) / 256, 256, 0, s1>>>(ei1, ew1, E1, cur, epk);
    }
    vpack_kernel<<<1, 512, 0, s1>>>(W2, Wlin, VT);
    cudaEventRecord(evJoin, s1);

    // ---- main stream: W split + GEMM1 (compute-bound, hides the CSR build)
    wsplit_kernel<<<16, 256>>>(W1, Whi, Wlo);
    int gemmBlocks = (n + 63) / 64;
    gemm_mma_kernel<<<gemmBlocks, 256, GEMM_SMEM_BYTES>>>(x, Whi, Wlo, buf0, n);

    // ---- join
    cudaStreamWaitEvent(0, evJoin, 0);

    // Fused CSR aggregate + relu + V projection (writes y2, zeroes c)
    {
        long long th = (long long)n * 32;
        scatter_csr_fused_kernel<<<(int)((th + 255) / 256), 256>>>(
            buf0, off, cnt, epk, VT, y2, c, n);
    }

    // Narrow scatter (layer 2 collapsed)
    {
        int threads = (E2 + 3) / 4;
        scatter4_kernel<<<(threads + 255) / 256, 256>>>(y2, ei2, ew2, c, E2);
    }

    // Pair epilogue
    pair_small_kernel<<<(P + 255) / 256, 256>>>(c, pe, out, P);
}

// round 12
// speedup vs baseline: 2.4367x; 1.3131x over previous
#include <cuda_runtime.h>
#include <cuda_fp16.h>
#include <cstdint>

#define HID 128
#define NMAX 100000
#define EMAX 800000

__device__ float  g_buf0[(size_t)NMAX * HID];  // xw1
__device__ float  g_y2  [(size_t)NMAX * 4];    // relu(h) @ V
__device__ float  g_c   [(size_t)NMAX * 4];    // layer-2 collapsed aggregate
__device__ float  g_VT  [4 * HID];             // (W2 @ WlinPacked)^T : VT[j][k]
__device__ ushort g_Wh  [128 * 136];           // W1 as fp16, padded [k][n]
__device__ int    g_cnt [NMAX];                // CSR degree
__device__ int    g_off [NMAX];                // CSR segment starts
__device__ int    g_cur [NMAX];                // CSR fill cursors
__device__ int    g_tot [1];                   // allocation counter
__device__ int2   g_epk [EMAX];                // CSR edges: {src, w bits}

__device__ __forceinline__ uint32_t smem_u32(const void* p) {
    uint32_t a;
    asm("{ .reg .u64 t; cvta.to.shared.u64 t, %1; cvt.u32.u64 %0, t; }"
        : "=r"(a) : "l"(p));
    return a;
}

#define LDM_X4(r0, r1, r2, r3, a)                                             \
    asm volatile("ldmatrix.sync.aligned.m8n8.x4.shared.b16 {%0,%1,%2,%3}, [%4];" \
                 : "=r"(r0), "=r"(r1), "=r"(r2), "=r"(r3) : "r"(a))
#define LDM_X4T(r0, r1, r2, r3, a)                                            \
    asm volatile("ldmatrix.sync.aligned.m8n8.x4.trans.shared.b16 {%0,%1,%2,%3}, [%4];" \
                 : "=r"(r0), "=r"(r1), "=r"(r2), "=r"(r3) : "r"(a))
#define MMA_F16(d, a, b)                                                      \
    asm volatile("mma.sync.aligned.m16n8k16.row.col.f32.f16.f16.f32 "         \
                 "{%0,%1,%2,%3}, {%4,%5,%6,%7}, {%8,%9}, {%0,%1,%2,%3};"      \
                 : "+f"((d)[0]), "+f"((d)[1]), "+f"((d)[2]), "+f"((d)[3])     \
                 : "r"((a)[0]), "r"((a)[1]), "r"((a)[2]), "r"((a)[3]),        \
                   "r"((b)[0]), "r"((b)[1]))

// ---------------------------------------------------------------------------
// Convert W1 to fp16 (rn), padded [k][136] layout.
// ---------------------------------------------------------------------------
__global__ void wconv_kernel(const float* __restrict__ W, ushort* __restrict__ Wh)
{
    int i = blockIdx.x * blockDim.x + threadIdx.x;   // 0..4095
    if (i >= 128 * 32) return;
    int k = i >> 5, q = i & 31;
    float4 v = __ldg((const float4*)(W + (size_t)k * HID) + q);
    __half2 p0 = __float22half2_rn(make_float2(v.x, v.y));
    __half2 p1 = __float22half2_rn(make_float2(v.z, v.w));
    uint2 pk = make_uint2(*(uint32_t*)&p0, *(uint32_t*)&p1);
    *(uint2*)(Wh + (size_t)k * 136 + q * 4) = pk;
}

// ---------------------------------------------------------------------------
// VT[j][k] = sum_c W2[k,c] * wl_j[c]. One warp per output (512 warps).
// ---------------------------------------------------------------------------
__global__ __launch_bounds__(256) void vpack_kernel(
    const float* __restrict__ W2, const float* __restrict__ Wlin,
    float* __restrict__ VT)
{
    int w = (int)((blockIdx.x * blockDim.x + threadIdx.x) >> 5);  // 0..511
    int lane = threadIdx.x & 31;
    if (w >= 512) return;
    int k = w >> 2, j = w & 3;
    const float* wl = Wlin + (j >> 1) * 256 + (j & 1) * 128;
    const float* wr = W2 + (size_t)k * HID;
    float4 a = __ldg((const float4*)wr + lane);
    float4 b = __ldg((const float4*)wl + lane);
    float acc = a.x * b.x + a.y * b.y + a.z * b.z + a.w * b.w;
#pragma unroll
    for (int o = 16; o > 0; o >>= 1)
        acc += __shfl_xor_sync(0xFFFFFFFFu, acc, o);
    if (lane == 0) VT[j * HID + k] = acc;
}

// ---------------------------------------------------------------------------
// CSR build: histogram -> warp-aggregated segment allocation -> reorder
// ---------------------------------------------------------------------------
__global__ void hist_kernel(const int* __restrict__ ei, int E, int* __restrict__ cnt)
{
    int i = blockIdx.x * blockDim.x + threadIdx.x;
    int e0 = i * 4;
    if (e0 >= E) return;
    if (e0 + 4 <= E) {
        int4 d = __ldg((const int4*)(ei + E) + i);
        atomicAdd(&cnt[d.x], 1); atomicAdd(&cnt[d.y], 1);
        atomicAdd(&cnt[d.z], 1); atomicAdd(&cnt[d.w], 1);
    } else {
        for (int e = e0; e < E; e++) atomicAdd(&cnt[__ldg(ei + E + e)], 1);
    }
}

__global__ __launch_bounds__(256) void alloc_kernel(
    const int* __restrict__ cnt, int* __restrict__ off, int* __restrict__ cur,
    int* __restrict__ total, int n)
{
    int i = blockIdx.x * blockDim.x + threadIdx.x;
    int lane = threadIdx.x & 31;
    int cv = (i < n) ? __ldg(cnt + i) : 0;
    int sc = cv;
#pragma unroll
    for (int o = 1; o < 32; o <<= 1) {
        int v = __shfl_up_sync(0xFFFFFFFFu, sc, o);
        if (lane >= o) sc += v;
    }
    int wsum = __shfl_sync(0xFFFFFFFFu, sc, 31);
    int base = 0;
    if (lane == 31 && wsum > 0) base = atomicAdd(total, wsum);
    base = __shfl_sync(0xFFFFFFFFu, base, 31);
    if (i < n) {
        int o = base + sc - cv;
        off[i] = o; cur[i] = o;
    }
}

__global__ void reorder_kernel(const int* __restrict__ ei,
                               const float* __restrict__ ew, int E,
                               int* __restrict__ cur, int2* __restrict__ epk)
{
    int i = blockIdx.x * blockDim.x + threadIdx.x;
    int e0 = i * 4;
    if (e0 >= E) return;
    if (e0 + 4 <= E) {
        int4   s4 = __ldg((const int4*)ei + i);
        int4   d4 = __ldg((const int4*)(ei + E) + i);
        float4 w4 = __ldg((const float4*)ew + i);
        int   s[4] = {s4.x, s4.y, s4.z, s4.w};
        int   d[4] = {d4.x, d4.y, d4.z, d4.w};
        float w[4] = {w4.x, w4.y, w4.z, w4.w};
#pragma unroll
        for (int j = 0; j < 4; j++) {
            int pos = atomicAdd(&cur[d[j]], 1);
            epk[pos] = make_int2(s[j], __float_as_int(w[j]));
        }
    } else {
        for (int e = e0; e < E; e++) {
            int pos = atomicAdd(&cur[__ldg(ei + E + e)], 1);
            epk[pos] = make_int2(__ldg(ei + e), __float_as_int(__ldg(ew + e)));
        }
    }
}

// ===========================================================================
// GEMM1 (HMMA fp16, single term): Y[n,128] = X @ W1.
// CTA: 64x128 tile, 8 warps (2m x 4n), warp tile 32x32. 4 CTAs/SM.
// rn fp16 rounding of X and W: end-to-end norm rel err ~1e-4 (vs 1e-3).
// ===========================================================================
#define LDS_ 136
#define OFF_X 0
#define OFF_W (64 * LDS_ * 2)                       // 17,408
#define GEMM_SMEM_BYTES (OFF_W + 128 * LDS_ * 2)    // 52,224 B
#define W_U4 (128 * LDS_ * 2 / 16)                  // 2176

__global__ __launch_bounds__(256, 4) void gemm_mma_kernel(
    const float* __restrict__ X, const ushort* __restrict__ Wh,
    float* __restrict__ Y, int n)
{
    extern __shared__ char sm[];
    const int t   = threadIdx.x;
    const int lid = t & 31;
    const int wid = t >> 5;
    const int row0 = blockIdx.x * 64;

    // Stage W (pre-converted fp16): straight uint4 copy
    {
        const uint4* w4 = (const uint4*)Wh;
        uint4* dw = (uint4*)(sm + OFF_W);
        for (int i = t; i < W_U4; i += 256) dw[i] = __ldg(w4 + i);
    }

    // Stage X tile as fp16
    for (int i = t; i < 64 * 32; i += 256) {
        int m = i >> 5, q = i & 31;
        int r = row0 + m;
        int rc = r < n ? r : 0;
        float4 v = __ldg((const float4*)(X + (size_t)rc * HID) + q);
        __half2 p0 = __float22half2_rn(make_float2(v.x, v.y));
        __half2 p1 = __float22half2_rn(make_float2(v.z, v.w));
        uint2 pk = make_uint2(*(uint32_t*)&p0, *(uint32_t*)&p1);
        *(uint2*)(sm + OFF_X + ((size_t)m * LDS_ + q * 4) * 2) = pk;
    }
    __syncthreads();

    const int wm = wid & 1;
    const int wn = wid >> 1;
    const int mat  = lid >> 3;
    const int rsel = (mat & 1) * 8 + (lid & 7);
    const int csel = (mat >> 1) * 8;

    const uint32_t sb = smem_u32(sm);
    uint32_t aP = sb + OFF_X + (uint32_t)(((wm * 32 + rsel) * LDS_ + csel) * 2);
    uint32_t bP = sb + OFF_W + (uint32_t)((rsel * LDS_ + wn * 32 + csel) * 2);

    float acc[2][4][4];
#pragma unroll
    for (int mi = 0; mi < 2; mi++)
#pragma unroll
        for (int nj = 0; nj < 4; nj++)
#pragma unroll
            for (int e = 0; e < 4; e++) acc[mi][nj][e] = 0.f;

#pragma unroll
    for (int ks = 0; ks < 8; ks++) {
        const uint32_t ao = ks * 32;
        const uint32_t bo = (uint32_t)(ks * 16 * LDS_ * 2);

        uint32_t av[2][4];
        LDM_X4(av[0][0], av[0][1], av[0][2], av[0][3], aP + ao);
        LDM_X4(av[1][0], av[1][1], av[1][2], av[1][3], aP + ao + 16 * LDS_ * 2);

        uint32_t bv[4][2];
#pragma unroll
        for (int g = 0; g < 2; g++) {
            LDM_X4T(bv[g * 2][0], bv[g * 2][1], bv[g * 2 + 1][0], bv[g * 2 + 1][1],
                    bP + bo + g * 32);
        }

#pragma unroll
        for (int mi = 0; mi < 2; mi++)
#pragma unroll
            for (int nj = 0; nj < 4; nj++)
                MMA_F16(acc[mi][nj], av[mi], bv[nj]);
    }

    const int g  = lid >> 2;
    const int c2 = (lid & 3) * 2;
#pragma unroll
    for (int mi = 0; mi < 2; mi++) {
        int rbase = row0 + wm * 32 + mi * 16;
        int r1 = rbase + g, r2 = rbase + g + 8;
#pragma unroll
        for (int nj = 0; nj < 4; nj++) {
            int col = wn * 32 + nj * 8 + c2;
            if (r1 < n)
                *(float2*)(Y + (size_t)r1 * HID + col) =
                    make_float2(acc[mi][nj][0], acc[mi][nj][1]);
            if (r2 < n)
                *(float2*)(Y + (size_t)r2 * HID + col) =
                    make_float2(acc[mi][nj][2], acc[mi][nj][3]);
        }
    }
}

// ---------------------------------------------------------------------------
// Fused CSR scatter + projection: one warp per dst node, MLP=8.
// ---------------------------------------------------------------------------
__global__ __launch_bounds__(256) void scatter_csr_fused_kernel(
    const float* __restrict__ F, const int* __restrict__ off,
    const int* __restrict__ cnt, const int2* __restrict__ epk,
    const float* __restrict__ VT,
    float* __restrict__ y2, float* __restrict__ c, int n)
{
    int node = (int)(((long long)blockIdx.x * blockDim.x + threadIdx.x) >> 5);
    int lane = threadIdx.x & 31;
    if (node >= n) return;

    float4 vv[4];
#pragma unroll
    for (int j = 0; j < 4; j++)
        vv[j] = __ldg((const float4*)(VT + j * HID) + lane);

    int b = __ldg(off + node);
    int e = b + __ldg(cnt + node);

    float4 acc = make_float4(0.f, 0.f, 0.f, 0.f);
    int i = b;
    for (; i + 8 <= e; i += 8) {
        int2 ed[8];
#pragma unroll
        for (int j = 0; j < 8; j++) ed[j] = __ldg(epk + i + j);
        float4 v[8];
#pragma unroll
        for (int j = 0; j < 8; j++)
            v[j] = __ldg((const float4*)(F + (size_t)ed[j].x * HID) + lane);
#pragma unroll
        for (int j = 0; j < 8; j++) {
            float w = __int_as_float(ed[j].y);
            acc.x = fmaf(w, v[j].x, acc.x); acc.y = fmaf(w, v[j].y, acc.y);
            acc.z = fmaf(w, v[j].z, acc.z); acc.w = fmaf(w, v[j].w, acc.w);
        }
    }
    for (; i + 4 <= e; i += 4) {
        int2 e0 = __ldg(epk + i),     e1 = __ldg(epk + i + 1);
        int2 e2 = __ldg(epk + i + 2), e3 = __ldg(epk + i + 3);
        float4 v0 = __ldg((const float4*)(F + (size_t)e0.x * HID) + lane);
        float4 v1 = __ldg((const float4*)(F + (size_t)e1.x * HID) + lane);
        float4 v2 = __ldg((const float4*)(F + (size_t)e2.x * HID) + lane);
        float4 v3 = __ldg((const float4*)(F + (size_t)e3.x * HID) + lane);
        float w0 = __int_as_float(e0.y), w1 = __int_as_float(e1.y);
        float w2 = __int_as_float(e2.y), w3 = __int_as_float(e3.y);
        acc.x = fmaf(w0, v0.x, fmaf(w1, v1.x, fmaf(w2, v2.x, fmaf(w3, v3.x, acc.x))));
        acc.y = fmaf(w0, v0.y, fmaf(w1, v1.y, fmaf(w2, v2.y, fmaf(w3, v3.y, acc.y))));
        acc.z = fmaf(w0, v0.z, fmaf(w1, v1.z, fmaf(w2, v2.z, fmaf(w3, v3.z, acc.z))));
        acc.w = fmaf(w0, v0.w, fmaf(w1, v1.w, fmaf(w2, v2.w, fmaf(w3, v3.w, acc.w))));
    }
    for (; i < e; i++) {
        int2 ed = __ldg(epk + i);
        float w = __int_as_float(ed.y);
        float4 v = __ldg((const float4*)(F + (size_t)ed.x * HID) + lane);
        acc.x = fmaf(w, v.x, acc.x); acc.y = fmaf(w, v.y, acc.y);
        acc.z = fmaf(w, v.z, acc.z); acc.w = fmaf(w, v.w, acc.w);
    }

    float rx = fmaxf(acc.x, 0.f), ry = fmaxf(acc.y, 0.f);
    float rz = fmaxf(acc.z, 0.f), rw = fmaxf(acc.w, 0.f);
    float d[4];
#pragma unroll
    for (int j = 0; j < 4; j++)
        d[j] = rx * vv[j].x + ry * vv[j].y + rz * vv[j].z + rw * vv[j].w;
#pragma unroll
    for (int o = 16; o > 0; o >>= 1) {
#pragma unroll
        for (int j = 0; j < 4; j++)
            d[j] += __shfl_xor_sync(0xFFFFFFFFu, d[j], o);
    }
    if (lane == 0) {
        ((float4*)y2)[node] = make_float4(d[0], d[1], d[2], d[3]);
        ((float4*)c)[node]  = make_float4(0.f, 0.f, 0.f, 0.f);
    }
}

// ---------------------------------------------------------------------------
// Narrow scatter (layer 2 collapsed): c[dst] += w_e * y2[src]. 4 edges/thread.
// ---------------------------------------------------------------------------
__global__ __launch_bounds__(256) void scatter4_kernel(
    const float* __restrict__ y2, const int* __restrict__ ei,
    const float* __restrict__ ew, float* __restrict__ c, int E)
{
    int tI = blockIdx.x * blockDim.x + threadIdx.x;
    int e0 = tI * 4;
    if (e0 >= E) return;

    if (e0 + 4 <= E) {
        int4   s4 = __ldg((const int4*)ei + tI);
        int4   d4 = __ldg((const int4*)(ei + E) + tI);
        float4 w4 = __ldg((const float4*)ew + tI);
        int   s[4] = {s4.x, s4.y, s4.z, s4.w};
        int   d[4] = {d4.x, d4.y, d4.z, d4.w};
        float w[4] = {w4.x, w4.y, w4.z, w4.w};
        float4 v[4];
#pragma unroll
        for (int j = 0; j < 4; j++) v[j] = __ldg((const float4*)y2 + s[j]);
#pragma unroll
        for (int j = 0; j < 4; j++) {
            v[j].x *= w[j]; v[j].y *= w[j]; v[j].z *= w[j]; v[j].w *= w[j];
            float* p = c + (size_t)d[j] * 4;
            asm volatile("red.global.add.v4.f32 [%0], {%1,%2,%3,%4};"
                         :: "l"(p), "f"(v[j].x), "f"(v[j].y), "f"(v[j].z), "f"(v[j].w)
                         : "memory");
        }
    } else {
        for (int e = e0; e < E; e++) {
            int   s = __ldg(ei + e);
            int   d = __ldg(ei + E + e);
            float w = __ldg(ew + e);
            float4 v = __ldg((const float4*)y2 + s);
            v.x *= w; v.y *= w; v.z *= w; v.w *= w;
            float* p = c + (size_t)d * 4;
            asm volatile("red.global.add.v4.f32 [%0], {%1,%2,%3,%4};"
                         :: "l"(p), "f"(v.x), "f"(v.y), "f"(v.z), "f"(v.w) : "memory");
        }
    }
}

// ---------------------------------------------------------------------------
// Pair epilogue: out[p] = (c[a].0 + c[b].1, c[a].2 + c[b].3)
// ---------------------------------------------------------------------------
__global__ __launch_bounds__(256) void pair_small_kernel(
    const float* __restrict__ c, const int* __restrict__ pe,
    float* __restrict__ out, int P)
{
    int p = blockIdx.x * blockDim.x + threadIdx.x;
    if (p >= P) return;
    int a = __ldg(pe + p);
    int b = __ldg(pe + P + p);
    float4 ca = __ldg((const float4*)c + a);
    float4 cb = __ldg((const float4*)c + b);
    ((float2*)out)[p] = make_float2(ca.x + cb.y, ca.z + cb.w);
}

// ---------------------------------------------------------------------------
// Launch: stream-fork so CSR build + vpack overlap the GEMM.
// ---------------------------------------------------------------------------
extern "C" void kernel_launch(void* const* d_in, const int* in_sizes, int n_in,
                              void* d_out, int out_size)
{
    const float* x    = (const float*)d_in[0];
    const int*   ei1  = (const int*)  d_in[1];
    const int*   ei2  = (const int*)  d_in[2];
    const float* ew1  = (const float*)d_in[3];
    const float* ew2  = (const float*)d_in[4];
    const int*   pe   = (const int*)  d_in[5];
    const float* W1   = (const float*)d_in[6];
    const float* W2   = (const float*)d_in[7];
    const float* Wlin = (const float*)d_in[8];
    float* out = (float*)d_out;

    int n  = in_sizes[0] / HID;
    int E1 = in_sizes[3];
    int E2 = in_sizes[4];
    int P  = in_sizes[5] / 2;

    void *p_buf0, *p_y2, *p_c, *p_VT, *p_Wh;
    void *p_cnt, *p_off, *p_cur, *p_tot, *p_epk;
    cudaGetSymbolAddress(&p_buf0, g_buf0);
    cudaGetSymbolAddress(&p_y2,   g_y2);
    cudaGetSymbolAddress(&p_c,    g_c);
    cudaGetSymbolAddress(&p_VT,   g_VT);
    cudaGetSymbolAddress(&p_Wh,   g_Wh);
    cudaGetSymbolAddress(&p_cnt,  g_cnt);
    cudaGetSymbolAddress(&p_off,  g_off);
    cudaGetSymbolAddress(&p_cur,  g_cur);
    cudaGetSymbolAddress(&p_tot,  g_tot);
    cudaGetSymbolAddress(&p_epk,  g_epk);
    float*  buf0 = (float*)p_buf0;
    float*  y2   = (float*)p_y2;
    float*  c    = (float*)p_c;
    float*  VT   = (float*)p_VT;
    ushort* Wh   = (ushort*)p_Wh;
    int*    cnt  = (int*)p_cnt;
    int*    off  = (int*)p_off;
    int*    cur  = (int*)p_cur;
    int*    tot  = (int*)p_tot;
    int2*   epk  = (int2*)p_epk;

    cudaFuncSetAttribute(gemm_mma_kernel,
        cudaFuncAttributeMaxDynamicSharedMemorySize, GEMM_SMEM_BYTES);

    static cudaStream_t s1 = nullptr;
    static cudaEvent_t evFork = nullptr, evJoin = nullptr;
    if (s1 == nullptr) {
        cudaStreamCreateWithFlags(&s1, cudaStreamNonBlocking);
        cudaEventCreateWithFlags(&evFork, cudaEventDisableTiming);
        cudaEventCreateWithFlags(&evJoin, cudaEventDisableTiming);
    }

    // ---- fork: side stream does CSR build + vpack
    cudaEventRecord(evFork, 0);
    cudaStreamWaitEvent(s1, evFork, 0);

    cudaMemsetAsync(cnt, 0, (size_t)n * sizeof(int), s1);
    cudaMemsetAsync(tot, 0, sizeof(int), s1);
    {
        int q = (E1 + 3) / 4;
        hist_kernel<<<(q + 255) / 256, 256, 0, s1>>>(ei1, E1, cnt);
        alloc_kernel<<<(n + 255) / 256, 256, 0, s1>>>(cnt, off, cur, tot, n);
        reorder_kernel<<<(q + 255) / 256, 256, 0, s1>>>(ei1, ew1, E1, cur, epk);
    }
    vpack_kernel<<<64, 256, 0, s1>>>(W2, Wlin, VT);
    cudaEventRecord(evJoin, s1);

    // ---- main stream: W convert + GEMM1
    wconv_kernel<<<16, 256>>>(W1, Wh);
    int gemmBlocks = (n + 63) / 64;
    gemm_mma_kernel<<<gemmBlocks, 256, GEMM_SMEM_BYTES>>>(x, Wh, buf0, n);

    // ---- join
    cudaStreamWaitEvent(0, evJoin, 0);

    // Fused CSR aggregate + relu + V projection (writes y2, zeroes c)
    {
        long long th = (long long)n * 32;
        scatter_csr_fused_kernel<<<(int)((th + 255) / 256), 256>>>(
            buf0, off, cnt, epk, VT, y2, c, n);
    }

    // Narrow scatter (layer 2 collapsed)
    {
        int threads = (E2 + 3) / 4;
        scatter4_kernel<<<(threads + 255) / 256, 256>>>(y2, ei2, ew2, c, E2);
    }

    // Pair epilogue
    pair_small_kernel<<<(P + 255) / 256, 256>>>(c, pe, out, P);
}

// round 13
// speedup vs baseline: 2.7217x; 1.1170x over previous
#include <cuda_runtime.h>
#include <cuda_fp16.h>
#include <cstdint>

#define HID 128
#define NMAX 100000
#define EMAX 800000

__device__ ushort g_buf0[(size_t)NMAX * HID];  // xw1 as fp16
__device__ float  g_y2  [(size_t)NMAX * 4];    // relu(h) @ V
__device__ float  g_c   [(size_t)NMAX * 4];    // layer-2 collapsed aggregate
__device__ float  g_VT  [4 * HID];             // (W2 @ WlinPacked)^T : VT[j][k]
__device__ ushort g_Wh  [128 * 136];           // W1 as fp16, padded [k][n]
__device__ int    g_cnt [NMAX];                // CSR degree
__device__ int    g_off [NMAX];                // CSR segment starts
__device__ int    g_cur [NMAX];                // CSR fill cursors
__device__ int    g_tot [1];                   // allocation counter
__device__ int2   g_epk [EMAX];                // CSR edges: {src, w bits}

__device__ __forceinline__ uint32_t smem_u32(const void* p) {
    uint32_t a;
    asm("{ .reg .u64 t; cvta.to.shared.u64 t, %1; cvt.u32.u64 %0, t; }"
        : "=r"(a) : "l"(p));
    return a;
}

#define LDM_X4(r0, r1, r2, r3, a)                                             \
    asm volatile("ldmatrix.sync.aligned.m8n8.x4.shared.b16 {%0,%1,%2,%3}, [%4];" \
                 : "=r"(r0), "=r"(r1), "=r"(r2), "=r"(r3) : "r"(a))
#define LDM_X4T(r0, r1, r2, r3, a)                                            \
    asm volatile("ldmatrix.sync.aligned.m8n8.x4.trans.shared.b16 {%0,%1,%2,%3}, [%4];" \
                 : "=r"(r0), "=r"(r1), "=r"(r2), "=r"(r3) : "r"(a))
#define MMA_F16(d, a, b)                                                      \
    asm volatile("mma.sync.aligned.m16n8k16.row.col.f32.f16.f16.f32 "         \
                 "{%0,%1,%2,%3}, {%4,%5,%6,%7}, {%8,%9}, {%0,%1,%2,%3};"      \
                 : "+f"((d)[0]), "+f"((d)[1]), "+f"((d)[2]), "+f"((d)[3])     \
                 : "r"((a)[0]), "r"((a)[1]), "r"((a)[2]), "r"((a)[3]),        \
                   "r"((b)[0]), "r"((b)[1]))

// ---------------------------------------------------------------------------
// Convert W1 to fp16 (rn), padded [k][136] layout.
// ---------------------------------------------------------------------------
__global__ void wconv_kernel(const float* __restrict__ W, ushort* __restrict__ Wh)
{
    int i = blockIdx.x * blockDim.x + threadIdx.x;   // 0..4095
    if (i >= 128 * 32) return;
    int k = i >> 5, q = i & 31;
    float4 v = __ldg((const float4*)(W + (size_t)k * HID) + q);
    __half2 p0 = __float22half2_rn(make_float2(v.x, v.y));
    __half2 p1 = __float22half2_rn(make_float2(v.z, v.w));
    uint2 pk = make_uint2(*(uint32_t*)&p0, *(uint32_t*)&p1);
    *(uint2*)(Wh + (size_t)k * 136 + q * 4) = pk;
}

// ---------------------------------------------------------------------------
// VT[j][k] = sum_c W2[k,c] * wl_j[c]. One warp per output (512 warps).
// ---------------------------------------------------------------------------
__global__ __launch_bounds__(256) void vpack_kernel(
    const float* __restrict__ W2, const float* __restrict__ Wlin,
    float* __restrict__ VT)
{
    int w = (int)((blockIdx.x * blockDim.x + threadIdx.x) >> 5);  // 0..511
    int lane = threadIdx.x & 31;
    if (w >= 512) return;
    int k = w >> 2, j = w & 3;
    const float* wl = Wlin + (j >> 1) * 256 + (j & 1) * 128;
    const float* wr = W2 + (size_t)k * HID;
    float4 a = __ldg((const float4*)wr + lane);
    float4 b = __ldg((const float4*)wl + lane);
    float acc = a.x * b.x + a.y * b.y + a.z * b.z + a.w * b.w;
#pragma unroll
    for (int o = 16; o > 0; o >>= 1)
        acc += __shfl_xor_sync(0xFFFFFFFFu, acc, o);
    if (lane == 0) VT[j * HID + k] = acc;
}

// ---------------------------------------------------------------------------
// CSR build: histogram -> warp-aggregated segment allocation -> reorder
// ---------------------------------------------------------------------------
__global__ void hist_kernel(const int* __restrict__ ei, int E, int* __restrict__ cnt)
{
    int i = blockIdx.x * blockDim.x + threadIdx.x;
    int e0 = i * 4;
    if (e0 >= E) return;
    if (e0 + 4 <= E) {
        int4 d = __ldg((const int4*)(ei + E) + i);
        atomicAdd(&cnt[d.x], 1); atomicAdd(&cnt[d.y], 1);
        atomicAdd(&cnt[d.z], 1); atomicAdd(&cnt[d.w], 1);
    } else {
        for (int e = e0; e < E; e++) atomicAdd(&cnt[__ldg(ei + E + e)], 1);
    }
}

__global__ __launch_bounds__(256) void alloc_kernel(
    const int* __restrict__ cnt, int* __restrict__ off, int* __restrict__ cur,
    int* __restrict__ total, int n)
{
    int i = blockIdx.x * blockDim.x + threadIdx.x;
    int lane = threadIdx.x & 31;
    int cv = (i < n) ? __ldg(cnt + i) : 0;
    int sc = cv;
#pragma unroll
    for (int o = 1; o < 32; o <<= 1) {
        int v = __shfl_up_sync(0xFFFFFFFFu, sc, o);
        if (lane >= o) sc += v;
    }
    int wsum = __shfl_sync(0xFFFFFFFFu, sc, 31);
    int base = 0;
    if (lane == 31 && wsum > 0) base = atomicAdd(total, wsum);
    base = __shfl_sync(0xFFFFFFFFu, base, 31);
    if (i < n) {
        int o = base + sc - cv;
        off[i] = o; cur[i] = o;
    }
}

__global__ void reorder_kernel(const int* __restrict__ ei,
                               const float* __restrict__ ew, int E,
                               int* __restrict__ cur, int2* __restrict__ epk)
{
    int i = blockIdx.x * blockDim.x + threadIdx.x;
    int e0 = i * 4;
    if (e0 >= E) return;
    if (e0 + 4 <= E) {
        int4   s4 = __ldg((const int4*)ei + i);
        int4   d4 = __ldg((const int4*)(ei + E) + i);
        float4 w4 = __ldg((const float4*)ew + i);
        int   s[4] = {s4.x, s4.y, s4.z, s4.w};
        int   d[4] = {d4.x, d4.y, d4.z, d4.w};
        float w[4] = {w4.x, w4.y, w4.z, w4.w};
#pragma unroll
        for (int j = 0; j < 4; j++) {
            int pos = atomicAdd(&cur[d[j]], 1);
            epk[pos] = make_int2(s[j], __float_as_int(w[j]));
        }
    } else {
        for (int e = e0; e < E; e++) {
            int pos = atomicAdd(&cur[__ldg(ei + E + e)], 1);
            epk[pos] = make_int2(__ldg(ei + e), __float_as_int(__ldg(ew + e)));
        }
    }
}

// ===========================================================================
// GEMM1 (HMMA fp16): Yh[n,128] (fp16) = X @ W1.
// CTA: 64x128 tile, 8 warps (2m x 4n), warp tile 32x32. 4 CTAs/SM.
// ===========================================================================
#define LDS_ 136
#define OFF_X 0
#define OFF_W (64 * LDS_ * 2)                       // 17,408
#define GEMM_SMEM_BYTES (OFF_W + 128 * LDS_ * 2)    // 52,224 B
#define W_U4 (128 * LDS_ * 2 / 16)                  // 2176

__global__ __launch_bounds__(256, 4) void gemm_mma_kernel(
    const float* __restrict__ X, const ushort* __restrict__ Wh,
    ushort* __restrict__ Yh, int n)
{
    extern __shared__ char sm[];
    const int t   = threadIdx.x;
    const int lid = t & 31;
    const int wid = t >> 5;
    const int row0 = blockIdx.x * 64;

    // Stage W (pre-converted fp16): straight uint4 copy
    {
        const uint4* w4 = (const uint4*)Wh;
        uint4* dw = (uint4*)(sm + OFF_W);
        for (int i = t; i < W_U4; i += 256) dw[i] = __ldg(w4 + i);
    }

    // Stage X tile as fp16
    for (int i = t; i < 64 * 32; i += 256) {
        int m = i >> 5, q = i & 31;
        int r = row0 + m;
        int rc = r < n ? r : 0;
        float4 v = __ldg((const float4*)(X + (size_t)rc * HID) + q);
        __half2 p0 = __float22half2_rn(make_float2(v.x, v.y));
        __half2 p1 = __float22half2_rn(make_float2(v.z, v.w));
        uint2 pk = make_uint2(*(uint32_t*)&p0, *(uint32_t*)&p1);
        *(uint2*)(sm + OFF_X + ((size_t)m * LDS_ + q * 4) * 2) = pk;
    }
    __syncthreads();

    const int wm = wid & 1;
    const int wn = wid >> 1;
    const int mat  = lid >> 3;
    const int rsel = (mat & 1) * 8 + (lid & 7);
    const int csel = (mat >> 1) * 8;

    const uint32_t sb = smem_u32(sm);
    uint32_t aP = sb + OFF_X + (uint32_t)(((wm * 32 + rsel) * LDS_ + csel) * 2);
    uint32_t bP = sb + OFF_W + (uint32_t)((rsel * LDS_ + wn * 32 + csel) * 2);

    float acc[2][4][4];
#pragma unroll
    for (int mi = 0; mi < 2; mi++)
#pragma unroll
        for (int nj = 0; nj < 4; nj++)
#pragma unroll
            for (int e = 0; e < 4; e++) acc[mi][nj][e] = 0.f;

#pragma unroll
    for (int ks = 0; ks < 8; ks++) {
        const uint32_t ao = ks * 32;
        const uint32_t bo = (uint32_t)(ks * 16 * LDS_ * 2);

        uint32_t av[2][4];
        LDM_X4(av[0][0], av[0][1], av[0][2], av[0][3], aP + ao);
        LDM_X4(av[1][0], av[1][1], av[1][2], av[1][3], aP + ao + 16 * LDS_ * 2);

        uint32_t bv[4][2];
#pragma unroll
        for (int g = 0; g < 2; g++) {
            LDM_X4T(bv[g * 2][0], bv[g * 2][1], bv[g * 2 + 1][0], bv[g * 2 + 1][1],
                    bP + bo + g * 32);
        }

#pragma unroll
        for (int mi = 0; mi < 2; mi++)
#pragma unroll
            for (int nj = 0; nj < 4; nj++)
                MMA_F16(acc[mi][nj], av[mi], bv[nj]);
    }

    // Epilogue: fp16 output (half2 stores; col is even -> 4B aligned)
    const int g  = lid >> 2;
    const int c2 = (lid & 3) * 2;
#pragma unroll
    for (int mi = 0; mi < 2; mi++) {
        int rbase = row0 + wm * 32 + mi * 16;
        int r1 = rbase + g, r2 = rbase + g + 8;
#pragma unroll
        for (int nj = 0; nj < 4; nj++) {
            int col = wn * 32 + nj * 8 + c2;
            if (r1 < n) {
                __half2 p = __float22half2_rn(make_float2(acc[mi][nj][0], acc[mi][nj][1]));
                *(uint32_t*)(Yh + (size_t)r1 * HID + col) = *(uint32_t*)&p;
            }
            if (r2 < n) {
                __half2 p = __float22half2_rn(make_float2(acc[mi][nj][2], acc[mi][nj][3]));
                *(uint32_t*)(Yh + (size_t)r2 * HID + col) = *(uint32_t*)&p;
            }
        }
    }
}

// ---------------------------------------------------------------------------
// Fused CSR scatter + projection: one warp per dst node, MLP=8.
// F is fp16 [n,128]; lane covers 4 features (uint2 = 8 B per edge per lane).
// ---------------------------------------------------------------------------
__global__ __launch_bounds__(256) void scatter_csr_fused_kernel(
    const ushort* __restrict__ F, const int* __restrict__ off,
    const int* __restrict__ cnt, const int2* __restrict__ epk,
    const float* __restrict__ VT,
    float* __restrict__ y2, float* __restrict__ c, int n)
{
    int node = (int)(((long long)blockIdx.x * blockDim.x + threadIdx.x) >> 5);
    int lane = threadIdx.x & 31;
    if (node >= n) return;

    float4 vv[4];
#pragma unroll
    for (int j = 0; j < 4; j++)
        vv[j] = __ldg((const float4*)(VT + j * HID) + lane);

    int b = __ldg(off + node);
    int e = b + __ldg(cnt + node);

    float4 acc = make_float4(0.f, 0.f, 0.f, 0.f);
    int i = b;
    for (; i + 8 <= e; i += 8) {
        int2 ed[8];
#pragma unroll
        for (int j = 0; j < 8; j++) ed[j] = __ldg(epk + i + j);
        uint2 pk[8];
#pragma unroll
        for (int j = 0; j < 8; j++)
            pk[j] = __ldg((const uint2*)(F + (size_t)ed[j].x * HID) + lane);
#pragma unroll
        for (int j = 0; j < 8; j++) {
            float w = __int_as_float(ed[j].y);
            float2 f0 = __half22float2(*(__half2*)&pk[j].x);
            float2 f1 = __half22float2(*(__half2*)&pk[j].y);
            acc.x = fmaf(w, f0.x, acc.x); acc.y = fmaf(w, f0.y, acc.y);
            acc.z = fmaf(w, f1.x, acc.z); acc.w = fmaf(w, f1.y, acc.w);
        }
    }
    for (; i < e; i++) {
        int2 ed = __ldg(epk + i);
        float w = __int_as_float(ed.y);
        uint2 pk = __ldg((const uint2*)(F + (size_t)ed.x * HID) + lane);
        float2 f0 = __half22float2(*(__half2*)&pk.x);
        float2 f1 = __half22float2(*(__half2*)&pk.y);
        acc.x = fmaf(w, f0.x, acc.x); acc.y = fmaf(w, f0.y, acc.y);
        acc.z = fmaf(w, f1.x, acc.z); acc.w = fmaf(w, f1.y, acc.w);
    }

    float rx = fmaxf(acc.x, 0.f), ry = fmaxf(acc.y, 0.f);
    float rz = fmaxf(acc.z, 0.f), rw = fmaxf(acc.w, 0.f);
    float d[4];
#pragma unroll
    for (int j = 0; j < 4; j++)
        d[j] = rx * vv[j].x + ry * vv[j].y + rz * vv[j].z + rw * vv[j].w;
#pragma unroll
    for (int o = 16; o > 0; o >>= 1) {
#pragma unroll
        for (int j = 0; j < 4; j++)
            d[j] += __shfl_xor_sync(0xFFFFFFFFu, d[j], o);
    }
    if (lane == 0) {
        ((float4*)y2)[node] = make_float4(d[0], d[1], d[2], d[3]);
        ((float4*)c)[node]  = make_float4(0.f, 0.f, 0.f, 0.f);
    }
}

// ---------------------------------------------------------------------------
// Narrow scatter (layer 2 collapsed): c[dst] += w_e * y2[src]. 4 edges/thread.
// ---------------------------------------------------------------------------
__global__ __launch_bounds__(256) void scatter4_kernel(
    const float* __restrict__ y2, const int* __restrict__ ei,
    const float* __restrict__ ew, float* __restrict__ c, int E)
{
    int tI = blockIdx.x * blockDim.x + threadIdx.x;
    int e0 = tI * 4;
    if (e0 >= E) return;

    if (e0 + 4 <= E) {
        int4   s4 = __ldg((const int4*)ei + tI);
        int4   d4 = __ldg((const int4*)(ei + E) + tI);
        float4 w4 = __ldg((const float4*)ew + tI);
        int   s[4] = {s4.x, s4.y, s4.z, s4.w};
        int   d[4] = {d4.x, d4.y, d4.z, d4.w};
        float w[4] = {w4.x, w4.y, w4.z, w4.w};
        float4 v[4];
#pragma unroll
        for (int j = 0; j < 4; j++) v[j] = __ldg((const float4*)y2 + s[j]);
#pragma unroll
        for (int j = 0; j < 4; j++) {
            v[j].x *= w[j]; v[j].y *= w[j]; v[j].z *= w[j]; v[j].w *= w[j];
            float* p = c + (size_t)d[j] * 4;
            asm volatile("red.global.add.v4.f32 [%0], {%1,%2,%3,%4};"
                         :: "l"(p), "f"(v[j].x), "f"(v[j].y), "f"(v[j].z), "f"(v[j].w)
                         : "memory");
        }
    } else {
        for (int e = e0; e < E; e++) {
            int   s = __ldg(ei + e);
            int   d = __ldg(ei + E + e);
            float w = __ldg(ew + e);
            float4 v = __ldg((const float4*)y2 + s);
            v.x *= w; v.y *= w; v.z *= w; v.w *= w;
            float* p = c + (size_t)d * 4;
            asm volatile("red.global.add.v4.f32 [%0], {%1,%2,%3,%4};"
                         :: "l"(p), "f"(v.x), "f"(v.y), "f"(v.z), "f"(v.w) : "memory");
        }
    }
}

// ---------------------------------------------------------------------------
// Pair epilogue: out[p] = (c[a].0 + c[b].1, c[a].2 + c[b].3)
// ---------------------------------------------------------------------------
__global__ __launch_bounds__(256) void pair_small_kernel(
    const float* __restrict__ c, const int* __restrict__ pe,
    float* __restrict__ out, int P)
{
    int p = blockIdx.x * blockDim.x + threadIdx.x;
    if (p >= P) return;
    int a = __ldg(pe + p);
    int b = __ldg(pe + P + p);
    float4 ca = __ldg((const float4*)c + a);
    float4 cb = __ldg((const float4*)c + b);
    ((float2*)out)[p] = make_float2(ca.x + cb.y, ca.z + cb.w);
}

// ---------------------------------------------------------------------------
// Launch: stream-fork so CSR build + vpack overlap the GEMM.
// ---------------------------------------------------------------------------
extern "C" void kernel_launch(void* const* d_in, const int* in_sizes, int n_in,
                              void* d_out, int out_size)
{
    const float* x    = (const float*)d_in[0];
    const int*   ei1  = (const int*)  d_in[1];
    const int*   ei2  = (const int*)  d_in[2];
    const float* ew1  = (const float*)d_in[3];
    const float* ew2  = (const float*)d_in[4];
    const int*   pe   = (const int*)  d_in[5];
    const float* W1   = (const float*)d_in[6];
    const float* W2   = (const float*)d_in[7];
    const float* Wlin = (const float*)d_in[8];
    float* out = (float*)d_out;

    int n  = in_sizes[0] / HID;
    int E1 = in_sizes[3];
    int E2 = in_sizes[4];
    int P  = in_sizes[5] / 2;

    void *p_buf0, *p_y2, *p_c, *p_VT, *p_Wh;
    void *p_cnt, *p_off, *p_cur, *p_tot, *p_epk;
    cudaGetSymbolAddress(&p_buf0, g_buf0);
    cudaGetSymbolAddress(&p_y2,   g_y2);
    cudaGetSymbolAddress(&p_c,    g_c);
    cudaGetSymbolAddress(&p_VT,   g_VT);
    cudaGetSymbolAddress(&p_Wh,   g_Wh);
    cudaGetSymbolAddress(&p_cnt,  g_cnt);
    cudaGetSymbolAddress(&p_off,  g_off);
    cudaGetSymbolAddress(&p_cur,  g_cur);
    cudaGetSymbolAddress(&p_tot,  g_tot);
    cudaGetSymbolAddress(&p_epk,  g_epk);
    ushort* buf0 = (ushort*)p_buf0;
    float*  y2   = (float*)p_y2;
    float*  c    = (float*)p_c;
    float*  VT   = (float*)p_VT;
    ushort* Wh   = (ushort*)p_Wh;
    int*    cnt  = (int*)p_cnt;
    int*    off  = (int*)p_off;
    int*    cur  = (int*)p_cur;
    int*    tot  = (int*)p_tot;
    int2*   epk  = (int2*)p_epk;

    cudaFuncSetAttribute(gemm_mma_kernel,
        cudaFuncAttributeMaxDynamicSharedMemorySize, GEMM_SMEM_BYTES);

    static cudaStream_t s1 = nullptr;
    static cudaEvent_t evFork = nullptr, evJoin = nullptr;
    if (s1 == nullptr) {
        cudaStreamCreateWithFlags(&s1, cudaStreamNonBlocking);
        cudaEventCreateWithFlags(&evFork, cudaEventDisableTiming);
        cudaEventCreateWithFlags(&evJoin, cudaEventDisableTiming);
    }

    // ---- fork: side stream does CSR build + vpack
    cudaEventRecord(evFork, 0);
    cudaStreamWaitEvent(s1, evFork, 0);

    cudaMemsetAsync(cnt, 0, (size_t)n * sizeof(int), s1);
    cudaMemsetAsync(tot, 0, sizeof(int), s1);
    {
        int q = (E1 + 3) / 4;
        hist_kernel<<<(q + 255) / 256, 256, 0, s1>>>(ei1, E1, cnt);
        alloc_kernel<<<(n + 255) / 256, 256, 0, s1>>>(cnt, off, cur, tot, n);
        reorder_kernel<<<(q + 255) / 256, 256, 0, s1>>>(ei1, ew1, E1, cur, epk);
    }
    vpack_kernel<<<64, 256, 0, s1>>>(W2, Wlin, VT);
    cudaEventRecord(evJoin, s1);

    // ---- main stream: W convert + GEMM1 (fp16 out)
    wconv_kernel<<<16, 256>>>(W1, Wh);
    int gemmBlocks = (n + 63) / 64;
    gemm_mma_kernel<<<gemmBlocks, 256, GEMM_SMEM_BYTES>>>(x, Wh, buf0, n);

    // ---- join
    cudaStreamWaitEvent(0, evJoin, 0);

    // Fused CSR aggregate + relu + V projection (writes y2, zeroes c)
    {
        long long th = (long long)n * 32;
        scatter_csr_fused_kernel<<<(int)((th + 255) / 256), 256>>>(
            buf0, off, cnt, epk, VT, y2, c, n);
    }

    // Narrow scatter (layer 2 collapsed)
    {
        int threads = (E2 + 3) / 4;
        scatter4_kernel<<<(threads + 255) / 256, 256>>>(y2, ei2, ew2, c, E2);
    }

    // Pair epilogue
    pair_small_kernel<<<(P + 255) / 256, 256>>>(c, pe, out, P);
}